// round 15
// baseline (speedup 1.0000x reference)
#include <cuda_runtime.h>
#include <cuda_bf16.h>
#include <math.h>
#include <stdint.h>

namespace {
constexpr int Bb  = 8;
constexpr int Tt  = 2048;
constexpr int Dd  = 512;
constexpr int BT  = Bb * Tt;
constexpr int CH  = 64;
constexpr int NCH = Tt / CH;   // 32
constexpr int DV  = 32;
constexpr int NVT = Dd / DV;   // 16

// ---- scan smem layout (byte offsets) ----
constexpr int OFF_S    = 0;              // float [32][520]   66560
constexpr int OFF_QS   = 66560;          // float [64][34]     8704
constexpr int OFF_VB   = 75264;          // float [64][34]     8704
constexpr int OFF_BETA = 83968;          // float [64]          256
constexpr int OFF_KH   = 84224;          // 2 half-slots x [64][160B] = 20480
constexpr int OFF_KL   = 104704;
constexpr int OFF_QH   = 125184;
constexpr int OFF_QL   = 145664;
constexpr int OFF_SH   = 166144;         // bf16 [32][136]     8704
constexpr int OFF_SL   = 174848;
constexpr int OFF_UH   = 183552;         // bf16 [32][72]      4608
constexpr int OFF_UL   = 188160;
constexpr int OFF_TH   = 192768;         // bf16 [64][72]      9216
constexpr int OFF_TL   = 201984;
constexpr int OFF_GH   = 211200;
constexpr int OFF_GL   = 220416;
constexpr int SCAN_SMEM = 229632;

constexpr int HSLOT = 10240;             // half-slot bytes (64 rows x 160 B)

// tgemm: 2 slots x (Ah|Al|Bh|Bl) each 128x40 halves = 10240 B
constexpr int TG_TILE  = 10240;
constexpr int TG_SLOT  = 4 * TG_TILE;
constexpr int TG_SMEM  = 2 * TG_SLOT;          // 81920 -> 2 CTAs/SM

// chunk_ag smem
constexpr int AG_TILE  = 17408;
constexpr int AG_AS    = 4 * AG_TILE;
constexpr int AG_TM    = AG_AS + 64 * 66 * 4;
constexpr int AG_WS    = AG_TM + 64 * 66 * 4;
constexpr int AG_SMEM  = AG_WS + 16 * 17 * 4;  // 104512
}

using ull = unsigned long long;

// ---------------- device scratch ----------------
__device__ float g_K[BT * Dd];
__device__ float g_V[BT * Dd];
__device__ float g_Beta[BT];
__device__ __nv_bfloat16 g_xh[BT * Dd];
__device__ __nv_bfloat16 g_xl[BT * Dd];
__device__ __nv_bfloat16 g_oh[BT * Dd];
__device__ __nv_bfloat16 g_ol[BT * Dd];
__device__ __nv_bfloat16 g_kh[BT * Dd];
__device__ __nv_bfloat16 g_kl[BT * Dd];
__device__ __nv_bfloat16 g_qh[BT * Dd];
__device__ __nv_bfloat16 g_ql[BT * Dd];
__device__ __nv_bfloat16 g_Th[Bb * NCH * CH * CH];
__device__ __nv_bfloat16 g_Tl[Bb * NCH * CH * CH];
__device__ __nv_bfloat16 g_Gh[Bb * NCH * CH * CH];
__device__ __nv_bfloat16 g_Gl[Bb * NCH * CH * CH];
__device__ __nv_bfloat16 g_wqh[Dd * Dd];
__device__ __nv_bfloat16 g_wql[Dd * Dd];
__device__ __nv_bfloat16 g_wkh[Dd * Dd];
__device__ __nv_bfloat16 g_wkl[Dd * Dd];
__device__ __nv_bfloat16 g_wvh[Dd * Dd];
__device__ __nv_bfloat16 g_wvl[Dd * Dd];
__device__ __nv_bfloat16 g_woh[Dd * Dd];
__device__ __nv_bfloat16 g_wol[Dd * Dd];

__device__ __forceinline__ uint32_t smem_u32(const void* p) {
    uint32_t a;
    asm("{ .reg .u64 t; cvta.to.shared.u64 t,%1; cvt.u32.u64 %0,t; }" : "=r"(a) : "l"(p));
    return a;
}
__device__ __forceinline__ void ldsm_x4(uint32_t* r, uint32_t addr) {
    asm volatile("ldmatrix.sync.aligned.m8n8.x4.shared.b16 {%0,%1,%2,%3}, [%4];"
                 : "=r"(r[0]), "=r"(r[1]), "=r"(r[2]), "=r"(r[3]) : "r"(addr));
}
__device__ __forceinline__ void ldsm_x4t(uint32_t* r, uint32_t addr) {
    asm volatile("ldmatrix.sync.aligned.m8n8.x4.trans.shared.b16 {%0,%1,%2,%3}, [%4];"
                 : "=r"(r[0]), "=r"(r[1]), "=r"(r[2]), "=r"(r[3]) : "r"(addr));
}
__device__ __forceinline__ void mma_bf16(float* d, const uint32_t* a,
                                         uint32_t b0, uint32_t b1) {
    asm volatile(
        "mma.sync.aligned.m16n8k16.row.col.f32.bf16.bf16.f32 "
        "{%0,%1,%2,%3}, {%4,%5,%6,%7}, {%8,%9}, {%0,%1,%2,%3};"
        : "+f"(d[0]), "+f"(d[1]), "+f"(d[2]), "+f"(d[3])
        : "r"(a[0]), "r"(a[1]), "r"(a[2]), "r"(a[3]), "r"(b0), "r"(b1));
}
__device__ __forceinline__ void cp16(uint32_t dst, const void* src) {
    asm volatile("cp.async.ca.shared.global [%0], [%1], 16;" :: "r"(dst), "l"(src));
}
__device__ __forceinline__ void split2(float x, unsigned short& h, unsigned short& l) {
    __nv_bfloat16 hh = __float2bfloat16(x);
    __nv_bfloat16 ll = __float2bfloat16(x - __bfloat162float(hh));
    h = __bfloat16_as_ushort(hh); l = __bfloat16_as_ushort(ll);
}
__device__ __forceinline__ void split4(float4 v, ull& h, ull& l) {
    unsigned short h0, h1, h2, h3, l0, l1, l2, l3;
    split2(v.x, h0, l0); split2(v.y, h1, l1);
    split2(v.z, h2, l2); split2(v.w, h3, l3);
    h = (ull)h0 | ((ull)h1 << 16) | ((ull)h2 << 32) | ((ull)h3 << 48);
    l = (ull)l0 | ((ull)l1 << 16) | ((ull)l2 << 32) | ((ull)l3 << 48);
}
__device__ __forceinline__ uint32_t pack2(float a, float b, bool hi) {
    unsigned short ha, la, hb, lb;
    split2(a, ha, la); split2(b, hb, lb);
    return hi ? ((uint32_t)ha | ((uint32_t)hb << 16))
              : ((uint32_t)la | ((uint32_t)lb << 16));
}

// ---------------- split fp32 -> bf16 hi/lo ----------------
__global__ __launch_bounds__(256) void split_kernel(
    const float* __restrict__ x, __nv_bfloat16* __restrict__ h,
    __nv_bfloat16* __restrict__ l, int n4)
{
    int i = blockIdx.x * 256 + threadIdx.x;
    if (i >= n4) return;
    float4 v = ((const float4*)x)[i];
    ull hw, lw; split4(v, hw, lw);
    ((ull*)h)[i] = hw;
    ((ull*)l)[i] = lw;
}

// ---------------- merged weight split ----------------
__global__ __launch_bounds__(256) void split_w_kernel(
    const float* __restrict__ Wq, const float* __restrict__ Wk,
    const float* __restrict__ Wv, const float* __restrict__ Wo,
    __nv_bfloat16* __restrict__ qh, __nv_bfloat16* __restrict__ ql,
    __nv_bfloat16* __restrict__ kh, __nv_bfloat16* __restrict__ kl,
    __nv_bfloat16* __restrict__ vh, __nv_bfloat16* __restrict__ vl,
    __nv_bfloat16* __restrict__ oh, __nv_bfloat16* __restrict__ ol,
    int n4)
{
    int i = blockIdx.x * 256 + threadIdx.x;
    if (i >= n4) return;
    const int w = blockIdx.y;
    const float* src = (w == 0) ? Wq : (w == 1) ? Wk : (w == 2) ? Wv : Wo;
    __nv_bfloat16* h = (w == 0) ? qh : (w == 1) ? kh : (w == 2) ? vh : oh;
    __nv_bfloat16* l = (w == 0) ? ql : (w == 1) ? kl : (w == 2) ? vl : ol;
    float4 v = ((const float4*)src)[i];
    ull hw, lw; split4(v, hw, lw);
    ((ull*)h)[i] = hw;
    ((ull*)l)[i] = lw;
}

// ---------------- HMMA split-bf16 GEMM body (2-slot cp.async, frag reuse) ----
__device__ __forceinline__ void tgemm_body(
    const __nv_bfloat16* __restrict__ Ah, const __nv_bfloat16* __restrict__ Al,
    const __nv_bfloat16* __restrict__ Bh, const __nv_bfloat16* __restrict__ Bl,
    const float* __restrict__ bias, float* __restrict__ C,
    __nv_bfloat16* __restrict__ Ch, __nv_bfloat16* __restrict__ Cl,
    int bm, int bn, char* tgs)
{
    const uint32_t sBase = smem_u32(tgs);
    const int tid = threadIdx.x, lane = tid & 31, wid = tid >> 5;
    const int wm = wid & 1, wn = wid >> 1;

    float d[4][4][4];
#pragma unroll
    for (int mt = 0; mt < 4; mt++)
#pragma unroll
        for (int nt = 0; nt < 4; nt++)
#pragma unroll
            for (int e = 0; e < 4; e++) d[mt][nt][e] = 0.f;

    uint32_t a_rel[4], b_rel[2];
    {
        const int ar = lane & 15, akoff = (lane >> 4) * 8;
#pragma unroll
        for (int mt = 0; mt < 4; mt++)
            a_rel[mt] = ((wm * 64 + mt * 16 + ar) * 40 + akoff) * 2;
        const int nrow = wn * 32 + ((lane >> 4) << 3) + (lane & 7);
        const int khalf = (lane >> 3) & 1;
#pragma unroll
        for (int np = 0; np < 2; np++)
            b_rel[np] = ((nrow + np * 16) * 40 + khalf * 8) * 2;
    }

    const int srow0 = tid >> 2,         sc0 = tid & 3;
    const int srow1 = (tid + 256) >> 2, sc1 = (tid + 256) & 3;
    const uint32_t st0 = srow0 * 80 + sc0 * 16;
    const uint32_t st1 = srow1 * 80 + sc1 * 16;

    auto issue = [&](int kt, int slot) {
        const uint32_t b0 = sBase + slot * TG_SLOT;
        const size_t ga0 = (size_t)(bm + srow0) * Dd + kt * 32 + sc0 * 8;
        const size_t ga1 = (size_t)(bm + srow1) * Dd + kt * 32 + sc1 * 8;
        const size_t gb0 = (size_t)(bn + srow0) * Dd + kt * 32 + sc0 * 8;
        const size_t gb1 = (size_t)(bn + srow1) * Dd + kt * 32 + sc1 * 8;
        cp16(b0 + st0,               Ah + ga0);
        cp16(b0 + st1,               Ah + ga1);
        cp16(b0 + TG_TILE + st0,     Al + ga0);
        cp16(b0 + TG_TILE + st1,     Al + ga1);
        cp16(b0 + 2 * TG_TILE + st0, Bh + gb0);
        cp16(b0 + 2 * TG_TILE + st1, Bh + gb1);
        cp16(b0 + 3 * TG_TILE + st0, Bl + gb0);
        cp16(b0 + 3 * TG_TILE + st1, Bl + gb1);
        asm volatile("cp.async.commit_group;");
    };

    issue(0, 0);
#pragma unroll 1
    for (int s = 0; s < 16; s++) {
        if (s + 1 < 16) {
            issue(s + 1, (s + 1) & 1);
            asm volatile("cp.async.wait_group 1;");
        } else {
            asm volatile("cp.async.wait_group 0;");
        }
        __syncthreads();
        const uint32_t slotB = sBase + (s & 1) * TG_SLOT;
#pragma unroll
        for (int ks = 0; ks < 2; ks++) {
            uint32_t aH[4][4], aL[4][4], bH[2][4], bX[2][4];
#pragma unroll
            for (int mt = 0; mt < 4; mt++)
                ldsm_x4(aH[mt], slotB + a_rel[mt] + ks * 32);
#pragma unroll
            for (int np = 0; np < 2; np++)
                ldsm_x4(bH[np], slotB + 2 * TG_TILE + b_rel[np] + ks * 32);
#pragma unroll
            for (int mt = 0; mt < 4; mt++)
#pragma unroll
                for (int nt = 0; nt < 4; nt++)
                    mma_bf16(d[mt][nt], aH[mt],
                             bH[nt >> 1][(nt & 1) * 2], bH[nt >> 1][(nt & 1) * 2 + 1]);
#pragma unroll
            for (int np = 0; np < 2; np++)
                ldsm_x4(bX[np], slotB + 3 * TG_TILE + b_rel[np] + ks * 32);
#pragma unroll
            for (int mt = 0; mt < 4; mt++)
#pragma unroll
                for (int nt = 0; nt < 4; nt++)
                    mma_bf16(d[mt][nt], aH[mt],
                             bX[nt >> 1][(nt & 1) * 2], bX[nt >> 1][(nt & 1) * 2 + 1]);
#pragma unroll
            for (int mt = 0; mt < 4; mt++)
                ldsm_x4(aL[mt], slotB + TG_TILE + a_rel[mt] + ks * 32);
#pragma unroll
            for (int mt = 0; mt < 4; mt++)
#pragma unroll
                for (int nt = 0; nt < 4; nt++)
                    mma_bf16(d[mt][nt], aL[mt],
                             bH[nt >> 1][(nt & 1) * 2], bH[nt >> 1][(nt & 1) * 2 + 1]);
        }
        __syncthreads();
    }

#pragma unroll
    for (int mt = 0; mt < 4; mt++) {
        const int r0 = bm + wm * 64 + mt * 16 + (lane >> 2);
#pragma unroll
        for (int nt = 0; nt < 4; nt++) {
            const int c0 = bn + wn * 32 + nt * 8 + (lane & 3) * 2;
            const float b0 = bias[c0], b1 = bias[c0 + 1];
            const float o00 = d[mt][nt][0] + b0, o01 = d[mt][nt][1] + b1;
            const float o10 = d[mt][nt][2] + b0, o11 = d[mt][nt][3] + b1;
            if (C) {
                *(float2*)&C[(size_t)r0 * Dd + c0] = make_float2(o00, o01);
                *(float2*)&C[(size_t)(r0 + 8) * Dd + c0] = make_float2(o10, o11);
            } else {
                unsigned short* ch = (unsigned short*)Ch;
                unsigned short* cl = (unsigned short*)Cl;
                *(uint32_t*)&ch[(size_t)r0 * Dd + c0] = pack2(o00, o01, true);
                *(uint32_t*)&cl[(size_t)r0 * Dd + c0] = pack2(o00, o01, false);
                *(uint32_t*)&ch[(size_t)(r0 + 8) * Dd + c0] = pack2(o10, o11, true);
                *(uint32_t*)&cl[(size_t)(r0 + 8) * Dd + c0] = pack2(o10, o11, false);
            }
        }
    }
}

__global__ __launch_bounds__(256, 2) void tgemm_mma_kernel(
    const __nv_bfloat16* __restrict__ Ah, const __nv_bfloat16* __restrict__ Al,
    const __nv_bfloat16* __restrict__ Bh, const __nv_bfloat16* __restrict__ Bl,
    const float* __restrict__ bias, float* __restrict__ C)
{
    extern __shared__ char tgs[];
    tgemm_body(Ah, Al, Bh, Bl, bias, C, nullptr, nullptr,
               blockIdx.y * 128, blockIdx.x * 128, tgs);
}

__global__ __launch_bounds__(256, 2) void tgemm_qkv_kernel(
    const __nv_bfloat16* __restrict__ Ah, const __nv_bfloat16* __restrict__ Al,
    const __nv_bfloat16* __restrict__ Bqh, const __nv_bfloat16* __restrict__ Bql,
    const __nv_bfloat16* __restrict__ Bkh, const __nv_bfloat16* __restrict__ Bkl,
    const __nv_bfloat16* __restrict__ Bvh, const __nv_bfloat16* __restrict__ Bvl,
    const float* __restrict__ bq, const float* __restrict__ bk,
    const float* __restrict__ bv,
    __nv_bfloat16* __restrict__ Qh, __nv_bfloat16* __restrict__ Ql,
    float* __restrict__ Ck, float* __restrict__ Cv)
{
    extern __shared__ char tgs[];
    const int gsel = blockIdx.x >> 2;
    const int bn = (blockIdx.x & 3) * 128;
    const __nv_bfloat16* Bh = (gsel == 0) ? Bqh : (gsel == 1) ? Bkh : Bvh;
    const __nv_bfloat16* Bl = (gsel == 0) ? Bql : (gsel == 1) ? Bkl : Bvl;
    const float* bias = (gsel == 0) ? bq : (gsel == 1) ? bk : bv;
    float* C = (gsel == 0) ? nullptr : (gsel == 1) ? Ck : Cv;
    tgemm_body(Ah, Al, Bh, Bl, bias, C,
               (gsel == 0) ? Qh : nullptr, (gsel == 0) ? Ql : nullptr,
               blockIdx.y * 128, bn, tgs);
}

// ---------------- l2norm + beta -> split K directly ----------------
__global__ __launch_bounds__(128) void norm_beta_kernel(
    const float* __restrict__ Kd, const float* __restrict__ wb,
    const float* __restrict__ bb, float* __restrict__ Beta,
    __nv_bfloat16* __restrict__ Kh, __nv_bfloat16* __restrict__ Kl)
{
    const int row = blockIdx.x, tid = threadIdx.x;
    float4 v = ((const float4*)(Kd + (size_t)row * Dd))[tid];
    float ss = v.x * v.x + v.y * v.y + v.z * v.z + v.w * v.w;
#pragma unroll
    for (int o = 16; o; o >>= 1) ss += __shfl_xor_sync(0xffffffffu, ss, o);
    __shared__ float red1[4];
    if ((tid & 31) == 0) red1[tid >> 5] = ss;
    __syncthreads();
    const float inv = 1.0f / fmaxf(sqrtf(red1[0] + red1[1] + red1[2] + red1[3]), 1e-12f);
    float4 w = ((const float4*)wb)[tid];
    float bd = v.x * w.x + v.y * w.y + v.z * w.z + v.w * w.w;
#pragma unroll
    for (int o = 16; o; o >>= 1) bd += __shfl_xor_sync(0xffffffffu, bd, o);
    __shared__ float red2[4];
    if ((tid & 31) == 0) red2[tid >> 5] = bd;
    __syncthreads();
    v.x *= inv; v.y *= inv; v.z *= inv; v.w *= inv;
    ull hw, lw; split4(v, hw, lw);
    ((ull*)(Kh + (size_t)row * Dd))[tid] = hw;
    ((ull*)(Kl + (size_t)row * Dd))[tid] = lw;
    if (tid == 0) {
        const float z = (red2[0] + red2[1] + red2[2] + red2[3]) * inv + bb[0];
        Beta[row] = 1.0f / (1.0f + expf(-z));
    }
}

// ---------------- chunk_ag: A,G via mma + T = (I+A)^-1 ----------------
__global__ __launch_bounds__(256) void chunk_ag_mma_kernel(
    const __nv_bfloat16* __restrict__ KhG, const __nv_bfloat16* __restrict__ KlG,
    const __nv_bfloat16* __restrict__ QhG, const __nv_bfloat16* __restrict__ QlG,
    const float* __restrict__ Betad,
    __nv_bfloat16* __restrict__ ThG, __nv_bfloat16* __restrict__ TlG,
    __nv_bfloat16* __restrict__ GhG, __nv_bfloat16* __restrict__ GlG)
{
    extern __shared__ char ags[];
    char* pKh = ags;               char* pKl = ags + AG_TILE;
    char* pQh = ags + 2 * AG_TILE; char* pQl = ags + 3 * AG_TILE;
    float* As = (float*)(ags + AG_AS);
    float* Tm = (float*)(ags + AG_TM);
    float* Ws = (float*)(ags + AG_WS);
    const uint32_t khB = smem_u32(pKh), klB = smem_u32(pKl);
    const uint32_t qhB = smem_u32(pQh), qlB = smem_u32(pQl);

    const int c = blockIdx.x, b = blockIdx.y;
    const int r0g = b * Tt + c * CH;
    const int tid = threadIdx.x, lane = tid & 31, wid = tid >> 5;
    const int mat = wid >> 2, mb = wid & 3;
    const int fr = lane >> 2, fc = 2 * (lane & 3);

    float cacc[8][4];
#pragma unroll
    for (int nb = 0; nb < 8; nb++)
#pragma unroll
        for (int e = 0; e < 4; e++) cacc[nb][e] = 0.f;

#pragma unroll 1
    for (int jt = 0; jt < 4; jt++) {
        if (jt) __syncthreads();
#pragma unroll
        for (int n = 0; n < 4; n++) {
            const int e = tid + n * 256;
            const int t = e >> 4, cc = e & 15;
            const uint32_t off = (uint32_t)t * 272u
                + ((uint32_t)(cc ^ ((t >> 3) & 1)) << 4);
            const size_t g = (size_t)(r0g + t) * Dd + jt * 128 + cc * 8;
            cp16(khB + off, KhG + g);
            cp16(klB + off, KlG + g);
            cp16(qhB + off, QhG + g);
            cp16(qlB + off, QlG + g);
        }
        asm volatile("cp.async.commit_group;");
        asm volatile("cp.async.wait_group 0;");
        __syncthreads();
#pragma unroll
        for (int p = 0; p < 3; p++) {
            const uint32_t aT = mat ? (p < 2 ? qhB : qlB) : (p < 2 ? khB : klB);
            const uint32_t bT = (p == 1) ? klB : khB;
#pragma unroll
            for (int k = 0; k < 8; k++) {
                uint32_t a[4];
                {
                    const int r = mb * 16 + (lane & 15);
                    const int cc = k * 2 + (lane >> 4);
                    ldsm_x4(a, aT + r * 272u + ((uint32_t)(cc ^ ((r >> 3) & 1)) << 4));
                }
#pragma unroll
                for (int nb4 = 0; nb4 < 4; nb4++) {
                    uint32_t bb[4];
                    const int r = nb4 * 16 + (lane & 7) + ((lane >> 4) << 3);
                    const int cc = k * 2 + ((lane >> 3) & 1);
                    ldsm_x4(bb, bT + r * 272u + ((uint32_t)(cc ^ ((r >> 3) & 1)) << 4));
                    mma_bf16(cacc[nb4 * 2 + 0], a, bb[0], bb[1]);
                    mma_bf16(cacc[nb4 * 2 + 1], a, bb[2], bb[3]);
                }
            }
        }
    }
    __syncthreads();

    const size_t gbase = ((size_t)(b * NCH) + c) * (CH * CH);
    const int t0r = mb * 16 + fr, t1r = t0r + 8;
    if (mat == 0) {
        const float bt0 = Betad[r0g + t0r], bt1 = Betad[r0g + t1r];
#pragma unroll
        for (int nb = 0; nb < 8; nb++) {
            const int j = nb * 8 + fc;
            float2 o0, o1;
            o0.x = (j     < t0r) ? bt0 * cacc[nb][0] : 0.f;
            o0.y = (j + 1 < t0r) ? bt0 * cacc[nb][1] : 0.f;
            o1.x = (j     < t1r) ? bt1 * cacc[nb][2] : 0.f;
            o1.y = (j + 1 < t1r) ? bt1 * cacc[nb][3] : 0.f;
            *(float2*)&As[t0r * 66 + j] = o0;
            *(float2*)&As[t1r * 66 + j] = o1;
        }
    } else {
        unsigned short* Gh = (unsigned short*)GhG;
        unsigned short* Gl = (unsigned short*)GlG;
#pragma unroll
        for (int nb = 0; nb < 8; nb++) {
            const int j = nb * 8 + fc;
            float v00 = (j     <= t0r) ? cacc[nb][0] : 0.f;
            float v01 = (j + 1 <= t0r) ? cacc[nb][1] : 0.f;
            float v10 = (j     <= t1r) ? cacc[nb][2] : 0.f;
            float v11 = (j + 1 <= t1r) ? cacc[nb][3] : 0.f;
            *(uint32_t*)&Gh[gbase + t0r * 64 + j] = pack2(v00, v01, true);
            *(uint32_t*)&Gl[gbase + t0r * 64 + j] = pack2(v00, v01, false);
            *(uint32_t*)&Gh[gbase + t1r * 64 + j] = pack2(v10, v11, true);
            *(uint32_t*)&Gl[gbase + t1r * 64 + j] = pack2(v10, v11, false);
        }
    }
    for (int e = tid; e < 64 * 66; e += 256) Tm[e] = 0.f;
    __syncthreads();

    if (wid < 4) {
        const int r = lane & 15;
        float Lr[16], val[16];
#pragma unroll
        for (int j = 0; j < 16; j++) Lr[j] = As[(wid * 16 + r) * 66 + wid * 16 + j];
#pragma unroll
        for (int cc = 0; cc < 16; cc++) val[cc] = (r == cc) ? 1.f : 0.f;
#pragma unroll
        for (int j = 0; j < 15; j++) {
#pragma unroll
            for (int cc = 0; cc < 16; cc++) {
                if (cc <= j) {
                    float tjc = __shfl_sync(0xffffffffu, val[cc], j);
                    if (r > j) val[cc] -= Lr[j] * tjc;
                }
            }
        }
        if (lane < 16) {
#pragma unroll
            for (int cc = 0; cc < 16; cc++)
                Tm[(wid * 16 + r) * 66 + wid * 16 + cc] = val[cc];
        }
    }
    __syncthreads();

    {
        const int oi[6] = {1, 2, 3, 2, 3, 3};
        const int oj[6] = {0, 0, 0, 1, 1, 2};
        const int r = tid >> 4, cc = tid & 15;
#pragma unroll 1
        for (int s6 = 0; s6 < 6; s6++) {
            const int bi = oi[s6], bj = oj[s6];
            float w = 0.f;
            for (int k = bj; k < bi; k++)
#pragma unroll
                for (int m = 0; m < 16; m++)
                    w += As[(bi * 16 + r) * 66 + k * 16 + m] *
                         Tm[(k * 16 + m) * 66 + bj * 16 + cc];
            Ws[r * 17 + cc] = w;
            __syncthreads();
            float t2 = 0.f;
#pragma unroll
            for (int m = 0; m < 16; m++)
                t2 += Tm[(bi * 16 + r) * 66 + bi * 16 + m] * Ws[m * 17 + cc];
            Tm[(bi * 16 + r) * 66 + bj * 16 + cc] = -t2;
            __syncthreads();
        }
    }

    {
        unsigned short* Th = (unsigned short*)ThG;
        unsigned short* Tl = (unsigned short*)TlG;
        for (int e = tid; e < 2048; e += 256) {
            const int t = e >> 5, j = (e & 31) * 2;
            *(uint32_t*)&Th[gbase + t * 64 + j] =
                pack2(Tm[t * 66 + j], Tm[t * 66 + j + 1], true);
            *(uint32_t*)&Tl[gbase + t * 64 + j] =
                pack2(Tm[t * 66 + j], Tm[t * 66 + j + 1], false);
        }
    }
}

// ---------------- chunked delta-rule scan: all-mma, pipelined phase A --------
__global__ __launch_bounds__(256) void scan_kernel(
    const __nv_bfloat16* __restrict__ KhG, const __nv_bfloat16* __restrict__ KlG,
    const __nv_bfloat16* __restrict__ QhG, const __nv_bfloat16* __restrict__ QlG,
    const __nv_bfloat16* __restrict__ ThG, const __nv_bfloat16* __restrict__ TlG,
    const __nv_bfloat16* __restrict__ GhG, const __nv_bfloat16* __restrict__ GlG,
    const float* __restrict__ Vd, const float* __restrict__ Betad,
    __nv_bfloat16* __restrict__ OhG, __nv_bfloat16* __restrict__ OlG)
{
    extern __shared__ char sraw[];
    float* S     = (float*)(sraw + OFF_S);
    float* QSm   = (float*)(sraw + OFF_QS);
    float* Vb    = (float*)(sraw + OFF_VB);
    float* betas = (float*)(sraw + OFF_BETA);
    char* pKh = sraw + OFF_KH;  char* pKl = sraw + OFF_KL;
    char* pQh = sraw + OFF_QH;  char* pQl = sraw + OFF_QL;
    char* pSh = sraw + OFF_SH;  char* pSl = sraw + OFF_SL;
    char* pUh = sraw + OFF_UH;  char* pUl = sraw + OFF_UL;
    char* pTh = sraw + OFF_TH;  char* pTl = sraw + OFF_TL;
    char* pGh = sraw + OFF_GH;  char* pGl = sraw + OFF_GL;
    const uint32_t khB = smem_u32(pKh), klB = smem_u32(pKl);
    const uint32_t qhB = smem_u32(pQh), qlB = smem_u32(pQl);
    const uint32_t shB = smem_u32(pSh), slB = smem_u32(pSl);
    const uint32_t uhB = smem_u32(pUh), ulB = smem_u32(pUl);
    const uint32_t thB = smem_u32(pTh), tlB = smem_u32(pTl);
    const uint32_t ghB = smem_u32(pGh), glB = smem_u32(pGl);

    const int b = blockIdx.y;
    const int i0 = blockIdx.x * DV;
    const int tid = threadIdx.x;
    const int lane = tid & 31, wid = tid >> 5;
    const int fr = lane >> 2, fc = 2 * (lane & 3);

    auto stu = [&](float v, int i, int t) {
        unsigned short h, l; split2(v, h, l);
        const uint32_t off = (uint32_t)i * 144u
            + ((uint32_t)((t >> 3) ^ ((i >> 3) & 1)) << 4) + (t & 7) * 2;
        *(unsigned short*)(pUh + off) = h;
        *(unsigned short*)(pUl + off) = l;
    };

    for (int e = tid; e < 32 * 520; e += 256) S[e] = 0.f;
    __syncthreads();

    for (int c = 0; c < NCH; c++) {
        const int r0g = b * Tt + c * CH;
        const size_t gbase = ((size_t)(b * NCH) + c) * (CH * CH);

        // half-tile phase-A staging: stage s covers cols jt*128 + half*64
        auto stageA = [&](int s) {
            const int jt = s >> 1, half = s & 1;
            const uint32_t so = (uint32_t)(s & 1) * HSLOT;
#pragma unroll
            for (int n = 0; n < 2; n++) {
                const int e = tid + n * 256;      // 512 chunks per array-half
                const int t = e >> 3, cc = e & 7;
                const uint32_t off = so + (uint32_t)t * 160u
                    + ((uint32_t)(cc ^ ((t >> 2) & 1)) << 4);
                const size_t g = (size_t)(r0g + t) * Dd + jt * 128 + half * 64 + cc * 8;
                cp16(khB + off, KhG + g);
                cp16(klB + off, KlG + g);
                cp16(qhB + off, QhG + g);
                cp16(qlB + off, QlG + g);
            }
            asm volatile("cp.async.commit_group;");
        };

        // chunk start: issue T/G, stage0; V/beta scalar loads
#pragma unroll
        for (int n = 0; n < 2; n++) {
            const int e = tid + n * 256;
            const int r = e >> 3, cc = e & 7;
            const uint32_t off = (uint32_t)r * 144u
                + ((uint32_t)(cc ^ ((r >> 3) & 1)) << 4);
            const size_t g = gbase + r * 64 + cc * 8;
            cp16(thB + off, ThG + g);
            cp16(tlB + off, TlG + g);
            cp16(ghB + off, GhG + g);
            cp16(glB + off, GlG + g);
        }
        asm volatile("cp.async.commit_group;");
        stageA(0);
        for (int e = tid; e < CH * DV; e += 256) {
            const int t = e >> 5, i = e & 31;
            Vb[t * 34 + i] = Vd[(size_t)(r0g + t) * Dd + i0 + i];
        }
        if (tid < 64) betas[tid] = Betad[r0g + tid];

        // ---- Phase A: 8 pipelined half-stages ----
        const int mat = wid >> 2;
        const int mb  = wid & 3;
        float cacc[4][4];
#pragma unroll
        for (int nb = 0; nb < 4; nb++)
#pragma unroll
            for (int e = 0; e < 4; e++) cacc[nb][e] = 0.f;

#pragma unroll 1
        for (int s = 0; s < 8; s++) {
            asm volatile("cp.async.wait_group 0;");
            __syncthreads();
            if (s + 1 < 8) stageA(s + 1);
            if ((s & 1) == 0) {
                // convert S tile jt = s>>1 to bf16 hi/lo
                const int jt = s >> 1;
#pragma unroll
                for (int n = 0; n < 4; n++) {
                    const int e = tid + n * 256;
                    const int i = e >> 5, d4 = (e & 31) * 4;
                    float4 v = *(const float4*)&S[i * 520 + jt * 128 + d4];
                    ull hw, lw; split4(v, hw, lw);
                    const uint32_t off = (uint32_t)i * 272u
                        + ((uint32_t)((d4 >> 3) ^ ((i >> 3) & 1)) << 4) + (d4 & 7) * 2;
                    *(ull*)(pSh + off) = hw;
                    *(ull*)(pSl + off) = lw;
                }
                __syncthreads();
            }
            const uint32_t so = (uint32_t)(s & 1) * HSLOT;
            const uint32_t aHi = (mat ? qhB : khB) + so;
            const uint32_t aLo = (mat ? qlB : klB) + so;
            const int half = s & 1;
#pragma unroll
            for (int k = 0; k < 4; k++) {
                uint32_t aH[4], aL[4], bH0[4], bH1[4], bX0[4], bX1[4];
                const int ra = mb * 16 + (lane & 15);
                const int ca = k * 2 + (lane >> 4);
                const uint32_t aoff = (uint32_t)ra * 160u
                    + ((uint32_t)(ca ^ ((ra >> 2) & 1)) << 4);
                const int kg = half * 4 + k;
                const int rb = (lane & 7) + ((lane >> 4) << 3);
                const int cb = kg * 2 + ((lane >> 3) & 1);
                const uint32_t boff0 = rb * 272u + ((uint32_t)(cb ^ ((rb >> 3) & 1)) << 4);
                const int rb2 = rb + 16;
                const uint32_t boff1 = rb2 * 272u + ((uint32_t)(cb ^ ((rb2 >> 3) & 1)) << 4);
                ldsm_x4(aH, aHi + aoff);
                ldsm_x4(bH0, shB + boff0);
                ldsm_x4(bH1, shB + boff1);
                mma_bf16(cacc[0], aH, bH0[0], bH0[1]);
                mma_bf16(cacc[1], aH, bH0[2], bH0[3]);
                mma_bf16(cacc[2], aH, bH1[0], bH1[1]);
                mma_bf16(cacc[3], aH, bH1[2], bH1[3]);
                ldsm_x4(bX0, slB + boff0);
                ldsm_x4(bX1, slB + boff1);
                mma_bf16(cacc[0], aH, bX0[0], bX0[1]);
                mma_bf16(cacc[1], aH, bX0[2], bX0[3]);
                mma_bf16(cacc[2], aH, bX1[0], bX1[1]);
                mma_bf16(cacc[3], aH, bX1[2], bX1[3]);
                ldsm_x4(aL, aLo + aoff);
                mma_bf16(cacc[0], aL, bH0[0], bH0[1]);
                mma_bf16(cacc[1], aL, bH0[2], bH0[3]);
                mma_bf16(cacc[2], aL, bH1[0], bH1[1]);
                mma_bf16(cacc[3], aL, bH1[2], bH1[3]);
            }
            __syncthreads();
        }

        // epilogue: warps 0-3 write rhs splits to UH/UL; warps 4-7 write QSm
        {
            const int t0r = mb * 16 + fr, t1r = t0r + 8;
            if (mat == 0) {
                const float b0v = betas[t0r], b1v = betas[t1r];
#pragma unroll
                for (int nb = 0; nb < 4; nb++) {
                    const int i = nb * 8 + fc;
                    float2 v0 = *(float2*)&Vb[t0r * 34 + i];
                    float2 v1 = *(float2*)&Vb[t1r * 34 + i];
                    stu(b0v * (v0.x - cacc[nb][0]), i,     t0r);
                    stu(b0v * (v0.y - cacc[nb][1]), i + 1, t0r);
                    stu(b1v * (v1.x - cacc[nb][2]), i,     t1r);
                    stu(b1v * (v1.y - cacc[nb][3]), i + 1, t1r);
                }
            } else {
#pragma unroll
                for (int nb = 0; nb < 4; nb++) {
                    const int i = nb * 8 + fc;
                    *(float2*)&QSm[t0r * 34 + i] = make_float2(cacc[nb][0], cacc[nb][1]);
                    *(float2*)&QSm[t1r * 34 + i] = make_float2(cacc[nb][2], cacc[nb][3]);
                }
            }
        }
        __syncthreads();

        // Phase B': U = T @ rhs (frag reuse); epilogue writes U splits in place
        {
            const int mb2 = wid >> 1, nh = wid & 1;
            float du[2][4];
#pragma unroll
            for (int n8 = 0; n8 < 2; n8++)
#pragma unroll
                for (int e = 0; e < 4; e++) du[n8][e] = 0.f;
#pragma unroll
            for (int k = 0; k < 4; k++) {
                uint32_t aH[4], aL[4], bH[4], bX[4];
                const int ra = mb2 * 16 + (lane & 15);
                const int ca = k * 2 + (lane >> 4);
                const uint32_t aoff = ra * 144u + ((uint32_t)(ca ^ ((ra >> 3) & 1)) << 4);
                const int rb = nh * 16 + (lane & 7) + ((lane >> 4) << 3);
                const int cb = k * 2 + ((lane >> 3) & 1);
                const uint32_t boff = rb * 144u + ((uint32_t)(cb ^ ((rb >> 3) & 1)) << 4);
                ldsm_x4(aH, thB + aoff);
                ldsm_x4(bH, uhB + boff);
                mma_bf16(du[0], aH, bH[0], bH[1]);
                mma_bf16(du[1], aH, bH[2], bH[3]);
                ldsm_x4(bX, ulB + boff);
                mma_bf16(du[0], aH, bX[0], bX[1]);
                mma_bf16(du[1], aH, bX[2], bX[3]);
                ldsm_x4(aL, tlB + aoff);
                mma_bf16(du[0], aL, bH[0], bH[1]);
                mma_bf16(du[1], aL, bH[2], bH[3]);
            }
            __syncthreads();   // all reads of UH/UL (rhs) done
            const int t0r = mb2 * 16 + fr, t1r = t0r + 8;
#pragma unroll
            for (int n8 = 0; n8 < 2; n8++) {
                const int i = nh * 16 + n8 * 8 + fc;
                stu(du[n8][0], i,     t0r);
                stu(du[n8][1], i + 1, t0r);
                stu(du[n8][2], i,     t1r);
                stu(du[n8][3], i + 1, t1r);
            }
        }
        __syncthreads();

        // issue phase-D jt=0 K staging (272-stride full tile) into K region
#pragma unroll
        for (int n = 0; n < 4; n++) {
            const int e = tid + n * 256;
            const int t = e >> 4, cc = e & 15;
            const uint32_t off = (uint32_t)t * 272u
                + ((uint32_t)(cc ^ ((t >> 3) & 1)) << 4);
            const size_t g = (size_t)(r0g + t) * Dd + cc * 8;
            cp16(khB + off, KhG + g);
            cp16(klB + off, KlG + g);
        }
        asm volatile("cp.async.commit_group;");

        // Phase C': O = QS + G @ U (frag reuse, split bf16 output)
        {
            const int mb2 = wid >> 1, nh = wid & 1;
            const int t0r = mb2 * 16 + fr, t1r = t0r + 8;
            float du[2][4];
#pragma unroll
            for (int n8 = 0; n8 < 2; n8++) {
                const int i = nh * 16 + n8 * 8 + fc;
                float2 q0 = *(float2*)&QSm[t0r * 34 + i];
                float2 q1 = *(float2*)&QSm[t1r * 34 + i];
                du[n8][0] = q0.x; du[n8][1] = q0.y;
                du[n8][2] = q1.x; du[n8][3] = q1.y;
            }
#pragma unroll
            for (int k = 0; k < 4; k++) {
                uint32_t aH[4], aL[4], bH[4], bX[4];
                const int ra = mb2 * 16 + (lane & 15);
                const int ca = k * 2 + (lane >> 4);
                const uint32_t aoff = ra * 144u + ((uint32_t)(ca ^ ((ra >> 3) & 1)) << 4);
                const int rb = nh * 16 + (lane & 7) + ((lane >> 4) << 3);
                const int cb = k * 2 + ((lane >> 3) & 1);
                const uint32_t boff = rb * 144u + ((uint32_t)(cb ^ ((rb >> 3) & 1)) << 4);
                ldsm_x4(aH, ghB + aoff);
                ldsm_x4(bH, uhB + boff);
                mma_bf16(du[0], aH, bH[0], bH[1]);
                mma_bf16(du[1], aH, bH[2], bH[3]);
                ldsm_x4(bX, ulB + boff);
                mma_bf16(du[0], aH, bX[0], bX[1]);
                mma_bf16(du[1], aH, bX[2], bX[3]);
                ldsm_x4(aL, glB + aoff);
                mma_bf16(du[0], aL, bH[0], bH[1]);
                mma_bf16(du[1], aL, bH[2], bH[3]);
            }
            unsigned short* oh = (unsigned short*)OhG;
            unsigned short* ol = (unsigned short*)OlG;
#pragma unroll
            for (int n8 = 0; n8 < 2; n8++) {
                const int i = nh * 16 + n8 * 8 + fc;
                const size_t g0 = (size_t)(r0g + t0r) * Dd + i0 + i;
                const size_t g1 = (size_t)(r0g + t1r) * Dd + i0 + i;
                *(uint32_t*)&oh[g0] = pack2(du[n8][0], du[n8][1], true);
                *(uint32_t*)&ol[g0] = pack2(du[n8][0], du[n8][1], false);
                *(uint32_t*)&oh[g1] = pack2(du[n8][2], du[n8][3], true);
                *(uint32_t*)&ol[g1] = pack2(du[n8][2], du[n8][3], false);
            }
        }

        // Phase D: S += U^T @ K (double-buffered staging K<->Q regions, frag reuse)
#pragma unroll 1
        for (int jt = 0; jt < 4; jt++) {
            const uint32_t curH = (jt & 1) ? qhB : khB;
            const uint32_t curL = (jt & 1) ? qlB : klB;
            if (jt + 1 < 4) {
                const uint32_t nxtH = ((jt + 1) & 1) ? qhB : khB;
                const uint32_t nxtL = ((jt + 1) & 1) ? qlB : klB;
#pragma unroll
                for (int n = 0; n < 4; n++) {
                    const int e = tid + n * 256;
                    const int t = e >> 4, cc = e & 15;
                    const uint32_t off = (uint32_t)t * 272u
                        + ((uint32_t)(cc ^ ((t >> 3) & 1)) << 4);
                    const size_t g = (size_t)(r0g + t) * Dd + (jt + 1) * 128 + cc * 8;
                    cp16(nxtH + off, KhG + g);
                    cp16(nxtL + off, KlG + g);
                }
                asm volatile("cp.async.commit_group;");
                asm volatile("cp.async.wait_group 1;");
            } else {
                asm volatile("cp.async.wait_group 0;");
            }
            __syncthreads();

            float cf[2][2][4];
            const int dbase = jt * 128 + wid * 16;
#pragma unroll
            for (int mi = 0; mi < 2; mi++)
#pragma unroll
                for (int n8 = 0; n8 < 2; n8++) {
                    const int i0r = mi * 16 + fr;
                    const int col = dbase + n8 * 8 + fc;
                    float2 x0 = *(float2*)&S[i0r * 520 + col];
                    float2 x1 = *(float2*)&S[(i0r + 8) * 520 + col];
                    cf[mi][n8][0] = x0.x; cf[mi][n8][1] = x0.y;
                    cf[mi][n8][2] = x1.x; cf[mi][n8][3] = x1.y;
                }
#pragma unroll
            for (int k = 0; k < 4; k++) {
                uint32_t aH0[4], aH1[4], aL0[4], aL1[4], bH[4], bX[4];
                const int r = lane & 15;
                const int ca = k * 2 + (lane >> 4);
                const uint32_t aoff0 = r * 144u + ((uint32_t)(ca ^ ((r >> 3) & 1)) << 4);
                const int r2 = 16 + (lane & 15);
                const uint32_t aoff1 = r2 * 144u + ((uint32_t)(ca ^ ((r2 >> 3) & 1)) << 4);
                const int tr = k * 16 + (lane & 15);
                const int cb = wid * 2 + (lane >> 4);
                const uint32_t boff = tr * 272u + ((uint32_t)(cb ^ ((tr >> 3) & 1)) << 4);
                ldsm_x4(aH0, uhB + aoff0);
                ldsm_x4(aH1, uhB + aoff1);
                ldsm_x4t(bH, curH + boff);
                mma_bf16(cf[0][0], aH0, bH[0], bH[1]);
                mma_bf16(cf[0][1], aH0, bH[2], bH[3]);
                mma_bf16(cf[1][0], aH1, bH[0], bH[1]);
                mma_bf16(cf[1][1], aH1, bH[2], bH[3]);
                ldsm_x4t(bX, curL + boff);
                mma_bf16(cf[0][0], aH0, bX[0], bX[1]);
                mma_bf16(cf[0][1], aH0, bX[2], bX[3]);
                mma_bf16(cf[1][0], aH1, bX[0], bX[1]);
                mma_bf16(cf[1][1], aH1, bX[2], bX[3]);
                ldsm_x4(aL0, ulB + aoff0);
                ldsm_x4(aL1, ulB + aoff1);
                mma_bf16(cf[0][0], aL0, bH[0], bH[1]);
                mma_bf16(cf[0][1], aL0, bH[2], bH[3]);
                mma_bf16(cf[1][0], aL1, bH[0], bH[1]);
                mma_bf16(cf[1][1], aL1, bH[2], bH[3]);
            }
#pragma unroll
            for (int mi = 0; mi < 2; mi++)
#pragma unroll
                for (int n8 = 0; n8 < 2; n8++) {
                    const int i0r = mi * 16 + fr;
                    const int col = dbase + n8 * 8 + fc;
                    *(float2*)&S[i0r * 520 + col] =
                        make_float2(cf[mi][n8][0], cf[mi][n8][1]);
                    *(float2*)&S[(i0r + 8) * 520 + col] =
                        make_float2(cf[mi][n8][2], cf[mi][n8][3]);
                }
            __syncthreads();
        }
    }
}

extern "C" void kernel_launch(void* const* d_in, const int* in_sizes, int n_in,
                              void* d_out, int out_size)
{
    const float* x     = (const float*)d_in[0];
    const float* Wq    = (const float*)d_in[1];
    const float* bq    = (const float*)d_in[2];
    const float* Wk    = (const float*)d_in[3];
    const float* bk    = (const float*)d_in[4];
    const float* Wv    = (const float*)d_in[5];
    const float* bv    = (const float*)d_in[6];
    const float* Wbeta = (const float*)d_in[7];
    const float* bbeta = (const float*)d_in[8];
    const float* Wo    = (const float*)d_in[9];
    const float* bo    = (const float*)d_in[10];
    float* out = (float*)d_out;

    float *pK, *pV, *pBeta;
    cudaGetSymbolAddress((void**)&pK, g_K);
    cudaGetSymbolAddress((void**)&pV, g_V);
    cudaGetSymbolAddress((void**)&pBeta, g_Beta);

    __nv_bfloat16 *pxh, *pxl, *poh, *pol, *pkh, *pkl, *pqh, *pql;
    __nv_bfloat16 *pTh, *pTl, *pGh, *pGl;
    __nv_bfloat16 *pwqh, *pwql, *pwkh, *pwkl, *pwvh, *pwvl, *pwoh, *pwol;
    cudaGetSymbolAddress((void**)&pxh, g_xh);
    cudaGetSymbolAddress((void**)&pxl, g_xl);
    cudaGetSymbolAddress((void**)&poh, g_oh);
    cudaGetSymbolAddress((void**)&pol, g_ol);
    cudaGetSymbolAddress((void**)&pkh, g_kh);
    cudaGetSymbolAddress((void**)&pkl, g_kl);
    cudaGetSymbolAddress((void**)&pqh, g_qh);
    cudaGetSymbolAddress((void**)&pql, g_ql);
    cudaGetSymbolAddress((void**)&pTh, g_Th);
    cudaGetSymbolAddress((void**)&pTl, g_Tl);
    cudaGetSymbolAddress((void**)&pGh, g_Gh);
    cudaGetSymbolAddress((void**)&pGl, g_Gl);
    cudaGetSymbolAddress((void**)&pwqh, g_wqh);
    cudaGetSymbolAddress((void**)&pwql, g_wql);
    cudaGetSymbolAddress((void**)&pwkh, g_wkh);
    cudaGetSymbolAddress((void**)&pwkl, g_wkl);
    cudaGetSymbolAddress((void**)&pwvh, g_wvh);
    cudaGetSymbolAddress((void**)&pwvl, g_wvl);
    cudaGetSymbolAddress((void**)&pwoh, g_woh);
    cudaGetSymbolAddress((void**)&pwol, g_wol);

    cudaFuncSetAttribute(scan_kernel,
                         cudaFuncAttributeMaxDynamicSharedMemorySize, SCAN_SMEM);
    cudaFuncSetAttribute(tgemm_mma_kernel,
                         cudaFuncAttributeMaxDynamicSharedMemorySize, TG_SMEM);
    cudaFuncSetAttribute(tgemm_qkv_kernel,
                         cudaFuncAttributeMaxDynamicSharedMemorySize, TG_SMEM);
    cudaFuncSetAttribute(chunk_ag_mma_kernel,
                         cudaFuncAttributeMaxDynamicSharedMemorySize, AG_SMEM);

    const int nx4 = BT * Dd / 4;
    const int nw4 = Dd * Dd / 4;
    split_kernel<<<(nx4 + 255) / 256, 256>>>(x, pxh, pxl, nx4);
    split_w_kernel<<<dim3((nw4 + 255) / 256, 4), 256>>>(
        Wq, Wk, Wv, Wo, pwqh, pwql, pwkh, pwkl, pwvh, pwvl, pwoh, pwol, nw4);

    tgemm_qkv_kernel<<<dim3(12, BT / 128), 256, TG_SMEM>>>(
        pxh, pxl, pwqh, pwql, pwkh, pwkl, pwvh, pwvl, bq, bk, bv,
        pqh, pql, pK, pV);

    norm_beta_kernel<<<BT, 128>>>(pK, Wbeta, bbeta, pBeta, pkh, pkl);

    chunk_ag_mma_kernel<<<dim3(NCH, Bb), 256, AG_SMEM>>>(
        pkh, pkl, pqh, pql, pBeta, pTh, pTl, pGh, pGl);

    scan_kernel<<<dim3(NVT, Bb), 256, SCAN_SMEM>>>(
        pkh, pkl, pqh, pql, pTh, pTl, pGh, pGl, pV, pBeta, poh, pol);

    tgemm_mma_kernel<<<dim3(4, BT / 128), 256, TG_SMEM>>>(
        poh, pol, pwoh, pwol, bo, out);
}

// round 16
// speedup vs baseline: 1.0349x; 1.0349x over previous
#include <cuda_runtime.h>
#include <cuda_bf16.h>
#include <math.h>
#include <stdint.h>

namespace {
constexpr int Bb  = 8;
constexpr int Tt  = 2048;
constexpr int Dd  = 512;
constexpr int BT  = Bb * Tt;
constexpr int CH  = 64;
constexpr int NCH = Tt / CH;   // 32
constexpr int DV  = 32;
constexpr int NVT = Dd / DV;   // 16

// ---- scan smem layout (byte offsets) ----
constexpr int OFF_S    = 0;              // float [32][520]
constexpr int OFF_QS   = 66560;          // float [64][34]
constexpr int OFF_VB   = 75264;          // float [64][34]
constexpr int OFF_BETA = 83968;          // float [64]
constexpr int OFF_KH   = 84224;          // bf16 [64][136]  17408
constexpr int OFF_KL   = 101632;
constexpr int OFF_QH   = 119040;
constexpr int OFF_QL   = 136448;
constexpr int OFF_SH   = 153856;         // bf16 [32][136]   8704
constexpr int OFF_SL   = 162560;
constexpr int OFF_UH   = 171264;         // bf16 [32][72]    4608
constexpr int OFF_UL   = 175872;
constexpr int OFF_TH   = 180480;         // bf16 [64][72]    9216
constexpr int OFF_TL   = 189696;
constexpr int OFF_GH   = 198912;
constexpr int OFF_GL   = 208128;
constexpr int SCAN_SMEM = 217344;

// tgemm: 2 slots x (Ah|Al|Bh|Bl) each 128x40 halves = 10240 B
constexpr int TG_TILE  = 10240;
constexpr int TG_SLOT  = 4 * TG_TILE;
constexpr int TG_SMEM  = 2 * TG_SLOT;          // 81920 -> 2 CTAs/SM

// chunk_ag smem
constexpr int AG_TILE  = 17408;
constexpr int AG_AS    = 4 * AG_TILE;
constexpr int AG_TM    = AG_AS + 64 * 66 * 4;
constexpr int AG_WS    = AG_TM + 64 * 66 * 4;
constexpr int AG_SMEM  = AG_WS + 16 * 17 * 4;  // 104512
}

using ull = unsigned long long;

// ---------------- device scratch ----------------
__device__ float g_K[BT * Dd];
__device__ float g_V[BT * Dd];
__device__ float g_Beta[BT];
__device__ __nv_bfloat16 g_xh[BT * Dd];
__device__ __nv_bfloat16 g_xl[BT * Dd];
__device__ __nv_bfloat16 g_oh[BT * Dd];
__device__ __nv_bfloat16 g_ol[BT * Dd];
__device__ __nv_bfloat16 g_kh[BT * Dd];
__device__ __nv_bfloat16 g_kl[BT * Dd];
__device__ __nv_bfloat16 g_qh[BT * Dd];
__device__ __nv_bfloat16 g_ql[BT * Dd];
__device__ __nv_bfloat16 g_Th[Bb * NCH * CH * CH];
__device__ __nv_bfloat16 g_Tl[Bb * NCH * CH * CH];
__device__ __nv_bfloat16 g_Gh[Bb * NCH * CH * CH];
__device__ __nv_bfloat16 g_Gl[Bb * NCH * CH * CH];
__device__ __nv_bfloat16 g_wqh[Dd * Dd];
__device__ __nv_bfloat16 g_wql[Dd * Dd];
__device__ __nv_bfloat16 g_wkh[Dd * Dd];
__device__ __nv_bfloat16 g_wkl[Dd * Dd];
__device__ __nv_bfloat16 g_wvh[Dd * Dd];
__device__ __nv_bfloat16 g_wvl[Dd * Dd];
__device__ __nv_bfloat16 g_woh[Dd * Dd];
__device__ __nv_bfloat16 g_wol[Dd * Dd];

__device__ __forceinline__ uint32_t smem_u32(const void* p) {
    uint32_t a;
    asm("{ .reg .u64 t; cvta.to.shared.u64 t,%1; cvt.u32.u64 %0,t; }" : "=r"(a) : "l"(p));
    return a;
}
__device__ __forceinline__ void ldsm_x4(uint32_t* r, uint32_t addr) {
    asm volatile("ldmatrix.sync.aligned.m8n8.x4.shared.b16 {%0,%1,%2,%3}, [%4];"
                 : "=r"(r[0]), "=r"(r[1]), "=r"(r[2]), "=r"(r[3]) : "r"(addr));
}
__device__ __forceinline__ void ldsm_x4t(uint32_t* r, uint32_t addr) {
    asm volatile("ldmatrix.sync.aligned.m8n8.x4.trans.shared.b16 {%0,%1,%2,%3}, [%4];"
                 : "=r"(r[0]), "=r"(r[1]), "=r"(r[2]), "=r"(r[3]) : "r"(addr));
}
__device__ __forceinline__ void mma_bf16(float* d, const uint32_t* a,
                                         uint32_t b0, uint32_t b1) {
    asm volatile(
        "mma.sync.aligned.m16n8k16.row.col.f32.bf16.bf16.f32 "
        "{%0,%1,%2,%3}, {%4,%5,%6,%7}, {%8,%9}, {%0,%1,%2,%3};"
        : "+f"(d[0]), "+f"(d[1]), "+f"(d[2]), "+f"(d[3])
        : "r"(a[0]), "r"(a[1]), "r"(a[2]), "r"(a[3]), "r"(b0), "r"(b1));
}
__device__ __forceinline__ void cp16(uint32_t dst, const void* src) {
    asm volatile("cp.async.ca.shared.global [%0], [%1], 16;" :: "r"(dst), "l"(src));
}
__device__ __forceinline__ void split2(float x, unsigned short& h, unsigned short& l) {
    __nv_bfloat16 hh = __float2bfloat16(x);
    __nv_bfloat16 ll = __float2bfloat16(x - __bfloat162float(hh));
    h = __bfloat16_as_ushort(hh); l = __bfloat16_as_ushort(ll);
}
__device__ __forceinline__ void split4(float4 v, ull& h, ull& l) {
    unsigned short h0, h1, h2, h3, l0, l1, l2, l3;
    split2(v.x, h0, l0); split2(v.y, h1, l1);
    split2(v.z, h2, l2); split2(v.w, h3, l3);
    h = (ull)h0 | ((ull)h1 << 16) | ((ull)h2 << 32) | ((ull)h3 << 48);
    l = (ull)l0 | ((ull)l1 << 16) | ((ull)l2 << 32) | ((ull)l3 << 48);
}
__device__ __forceinline__ uint32_t pack2(float a, float b, bool hi) {
    unsigned short ha, la, hb, lb;
    split2(a, ha, la); split2(b, hb, lb);
    return hi ? ((uint32_t)ha | ((uint32_t)hb << 16))
              : ((uint32_t)la | ((uint32_t)lb << 16));
}

// ---------------- split fp32 -> bf16 hi/lo ----------------
__global__ __launch_bounds__(256) void split_kernel(
    const float* __restrict__ x, __nv_bfloat16* __restrict__ h,
    __nv_bfloat16* __restrict__ l, int n4)
{
    int i = blockIdx.x * 256 + threadIdx.x;
    if (i >= n4) return;
    float4 v = ((const float4*)x)[i];
    ull hw, lw; split4(v, hw, lw);
    ((ull*)h)[i] = hw;
    ((ull*)l)[i] = lw;
}

// ---------------- merged weight split ----------------
__global__ __launch_bounds__(256) void split_w_kernel(
    const float* __restrict__ Wq, const float* __restrict__ Wk,
    const float* __restrict__ Wv, const float* __restrict__ Wo,
    __nv_bfloat16* __restrict__ qh, __nv_bfloat16* __restrict__ ql,
    __nv_bfloat16* __restrict__ kh, __nv_bfloat16* __restrict__ kl,
    __nv_bfloat16* __restrict__ vh, __nv_bfloat16* __restrict__ vl,
    __nv_bfloat16* __restrict__ oh, __nv_bfloat16* __restrict__ ol,
    int n4)
{
    int i = blockIdx.x * 256 + threadIdx.x;
    if (i >= n4) return;
    const int w = blockIdx.y;
    const float* src = (w == 0) ? Wq : (w == 1) ? Wk : (w == 2) ? Wv : Wo;
    __nv_bfloat16* h = (w == 0) ? qh : (w == 1) ? kh : (w == 2) ? vh : oh;
    __nv_bfloat16* l = (w == 0) ? ql : (w == 1) ? kl : (w == 2) ? vl : ol;
    float4 v = ((const float4*)src)[i];
    ull hw, lw; split4(v, hw, lw);
    ((ull*)h)[i] = hw;
    ((ull*)l)[i] = lw;
}

// ---------------- HMMA split-bf16 GEMM body (2-slot cp.async, frag reuse) ----
__device__ __forceinline__ void tgemm_body(
    const __nv_bfloat16* __restrict__ Ah, const __nv_bfloat16* __restrict__ Al,
    const __nv_bfloat16* __restrict__ Bh, const __nv_bfloat16* __restrict__ Bl,
    const float* __restrict__ bias, float* __restrict__ C,
    __nv_bfloat16* __restrict__ Ch, __nv_bfloat16* __restrict__ Cl,
    int bm, int bn, char* tgs)
{
    const uint32_t sBase = smem_u32(tgs);
    const int tid = threadIdx.x, lane = tid & 31, wid = tid >> 5;
    const int wm = wid & 1, wn = wid >> 1;

    float d[4][4][4];
#pragma unroll
    for (int mt = 0; mt < 4; mt++)
#pragma unroll
        for (int nt = 0; nt < 4; nt++)
#pragma unroll
            for (int e = 0; e < 4; e++) d[mt][nt][e] = 0.f;

    uint32_t a_rel[4], b_rel[2];
    {
        const int ar = lane & 15, akoff = (lane >> 4) * 8;
#pragma unroll
        for (int mt = 0; mt < 4; mt++)
            a_rel[mt] = ((wm * 64 + mt * 16 + ar) * 40 + akoff) * 2;
        const int nrow = wn * 32 + ((lane >> 4) << 3) + (lane & 7);
        const int khalf = (lane >> 3) & 1;
#pragma unroll
        for (int np = 0; np < 2; np++)
            b_rel[np] = ((nrow + np * 16) * 40 + khalf * 8) * 2;
    }

    const int srow0 = tid >> 2,         sc0 = tid & 3;
    const int srow1 = (tid + 256) >> 2, sc1 = (tid + 256) & 3;
    const uint32_t st0 = srow0 * 80 + sc0 * 16;
    const uint32_t st1 = srow1 * 80 + sc1 * 16;

    auto issue = [&](int kt, int slot) {
        const uint32_t b0 = sBase + slot * TG_SLOT;
        const size_t ga0 = (size_t)(bm + srow0) * Dd + kt * 32 + sc0 * 8;
        const size_t ga1 = (size_t)(bm + srow1) * Dd + kt * 32 + sc1 * 8;
        const size_t gb0 = (size_t)(bn + srow0) * Dd + kt * 32 + sc0 * 8;
        const size_t gb1 = (size_t)(bn + srow1) * Dd + kt * 32 + sc1 * 8;
        cp16(b0 + st0,               Ah + ga0);
        cp16(b0 + st1,               Ah + ga1);
        cp16(b0 + TG_TILE + st0,     Al + ga0);
        cp16(b0 + TG_TILE + st1,     Al + ga1);
        cp16(b0 + 2 * TG_TILE + st0, Bh + gb0);
        cp16(b0 + 2 * TG_TILE + st1, Bh + gb1);
        cp16(b0 + 3 * TG_TILE + st0, Bl + gb0);
        cp16(b0 + 3 * TG_TILE + st1, Bl + gb1);
        asm volatile("cp.async.commit_group;");
    };

    issue(0, 0);
#pragma unroll 1
    for (int s = 0; s < 16; s++) {
        if (s + 1 < 16) {
            issue(s + 1, (s + 1) & 1);
            asm volatile("cp.async.wait_group 1;");
        } else {
            asm volatile("cp.async.wait_group 0;");
        }
        __syncthreads();
        const uint32_t slotB = sBase + (s & 1) * TG_SLOT;
#pragma unroll
        for (int ks = 0; ks < 2; ks++) {
            uint32_t aH[4][4], aL[4][4], bH[2][4], bX[2][4];
#pragma unroll
            for (int mt = 0; mt < 4; mt++)
                ldsm_x4(aH[mt], slotB + a_rel[mt] + ks * 32);
#pragma unroll
            for (int np = 0; np < 2; np++)
                ldsm_x4(bH[np], slotB + 2 * TG_TILE + b_rel[np] + ks * 32);
#pragma unroll
            for (int mt = 0; mt < 4; mt++)
#pragma unroll
                for (int nt = 0; nt < 4; nt++)
                    mma_bf16(d[mt][nt], aH[mt],
                             bH[nt >> 1][(nt & 1) * 2], bH[nt >> 1][(nt & 1) * 2 + 1]);
#pragma unroll
            for (int np = 0; np < 2; np++)
                ldsm_x4(bX[np], slotB + 3 * TG_TILE + b_rel[np] + ks * 32);
#pragma unroll
            for (int mt = 0; mt < 4; mt++)
#pragma unroll
                for (int nt = 0; nt < 4; nt++)
                    mma_bf16(d[mt][nt], aH[mt],
                             bX[nt >> 1][(nt & 1) * 2], bX[nt >> 1][(nt & 1) * 2 + 1]);
#pragma unroll
            for (int mt = 0; mt < 4; mt++)
                ldsm_x4(aL[mt], slotB + TG_TILE + a_rel[mt] + ks * 32);
#pragma unroll
            for (int mt = 0; mt < 4; mt++)
#pragma unroll
                for (int nt = 0; nt < 4; nt++)
                    mma_bf16(d[mt][nt], aL[mt],
                             bH[nt >> 1][(nt & 1) * 2], bH[nt >> 1][(nt & 1) * 2 + 1]);
        }
        __syncthreads();
    }

#pragma unroll
    for (int mt = 0; mt < 4; mt++) {
        const int r0 = bm + wm * 64 + mt * 16 + (lane >> 2);
#pragma unroll
        for (int nt = 0; nt < 4; nt++) {
            const int c0 = bn + wn * 32 + nt * 8 + (lane & 3) * 2;
            const float b0 = bias[c0], b1 = bias[c0 + 1];
            const float o00 = d[mt][nt][0] + b0, o01 = d[mt][nt][1] + b1;
            const float o10 = d[mt][nt][2] + b0, o11 = d[mt][nt][3] + b1;
            if (C) {
                *(float2*)&C[(size_t)r0 * Dd + c0] = make_float2(o00, o01);
                *(float2*)&C[(size_t)(r0 + 8) * Dd + c0] = make_float2(o10, o11);
            } else {
                unsigned short* ch = (unsigned short*)Ch;
                unsigned short* cl = (unsigned short*)Cl;
                *(uint32_t*)&ch[(size_t)r0 * Dd + c0] = pack2(o00, o01, true);
                *(uint32_t*)&cl[(size_t)r0 * Dd + c0] = pack2(o00, o01, false);
                *(uint32_t*)&ch[(size_t)(r0 + 8) * Dd + c0] = pack2(o10, o11, true);
                *(uint32_t*)&cl[(size_t)(r0 + 8) * Dd + c0] = pack2(o10, o11, false);
            }
        }
    }
}

__global__ __launch_bounds__(256, 2) void tgemm_mma_kernel(
    const __nv_bfloat16* __restrict__ Ah, const __nv_bfloat16* __restrict__ Al,
    const __nv_bfloat16* __restrict__ Bh, const __nv_bfloat16* __restrict__ Bl,
    const float* __restrict__ bias, float* __restrict__ C)
{
    extern __shared__ char tgs[];
    tgemm_body(Ah, Al, Bh, Bl, bias, C, nullptr, nullptr,
               blockIdx.y * 128, blockIdx.x * 128, tgs);
}

__global__ __launch_bounds__(256, 2) void tgemm_qkv_kernel(
    const __nv_bfloat16* __restrict__ Ah, const __nv_bfloat16* __restrict__ Al,
    const __nv_bfloat16* __restrict__ Bqh, const __nv_bfloat16* __restrict__ Bql,
    const __nv_bfloat16* __restrict__ Bkh, const __nv_bfloat16* __restrict__ Bkl,
    const __nv_bfloat16* __restrict__ Bvh, const __nv_bfloat16* __restrict__ Bvl,
    const float* __restrict__ bq, const float* __restrict__ bk,
    const float* __restrict__ bv,
    __nv_bfloat16* __restrict__ Qh, __nv_bfloat16* __restrict__ Ql,
    float* __restrict__ Ck, float* __restrict__ Cv)
{
    extern __shared__ char tgs[];
    const int gsel = blockIdx.x >> 2;
    const int bn = (blockIdx.x & 3) * 128;
    const __nv_bfloat16* Bh = (gsel == 0) ? Bqh : (gsel == 1) ? Bkh : Bvh;
    const __nv_bfloat16* Bl = (gsel == 0) ? Bql : (gsel == 1) ? Bkl : Bvl;
    const float* bias = (gsel == 0) ? bq : (gsel == 1) ? bk : bv;
    float* C = (gsel == 0) ? nullptr : (gsel == 1) ? Ck : Cv;
    tgemm_body(Ah, Al, Bh, Bl, bias, C,
               (gsel == 0) ? Qh : nullptr, (gsel == 0) ? Ql : nullptr,
               blockIdx.y * 128, bn, tgs);
}

// ---------------- l2norm + beta -> split K directly ----------------
__global__ __launch_bounds__(128) void norm_beta_kernel(
    const float* __restrict__ Kd, const float* __restrict__ wb,
    const float* __restrict__ bb, float* __restrict__ Beta,
    __nv_bfloat16* __restrict__ Kh, __nv_bfloat16* __restrict__ Kl)
{
    const int row = blockIdx.x, tid = threadIdx.x;
    float4 v = ((const float4*)(Kd + (size_t)row * Dd))[tid];
    float ss = v.x * v.x + v.y * v.y + v.z * v.z + v.w * v.w;
#pragma unroll
    for (int o = 16; o; o >>= 1) ss += __shfl_xor_sync(0xffffffffu, ss, o);
    __shared__ float red1[4];
    if ((tid & 31) == 0) red1[tid >> 5] = ss;
    __syncthreads();
    const float inv = 1.0f / fmaxf(sqrtf(red1[0] + red1[1] + red1[2] + red1[3]), 1e-12f);
    float4 w = ((const float4*)wb)[tid];
    float bd = v.x * w.x + v.y * w.y + v.z * w.z + v.w * w.w;
#pragma unroll
    for (int o = 16; o; o >>= 1) bd += __shfl_xor_sync(0xffffffffu, bd, o);
    __shared__ float red2[4];
    if ((tid & 31) == 0) red2[tid >> 5] = bd;
    __syncthreads();
    v.x *= inv; v.y *= inv; v.z *= inv; v.w *= inv;
    ull hw, lw; split4(v, hw, lw);
    ((ull*)(Kh + (size_t)row * Dd))[tid] = hw;
    ((ull*)(Kl + (size_t)row * Dd))[tid] = lw;
    if (tid == 0) {
        const float z = (red2[0] + red2[1] + red2[2] + red2[3]) * inv + bb[0];
        Beta[row] = 1.0f / (1.0f + expf(-z));
    }
}

// ---------------- chunk_ag: A,G via mma + T = (I+A)^-1 ----------------
__global__ __launch_bounds__(256) void chunk_ag_mma_kernel(
    const __nv_bfloat16* __restrict__ KhG, const __nv_bfloat16* __restrict__ KlG,
    const __nv_bfloat16* __restrict__ QhG, const __nv_bfloat16* __restrict__ QlG,
    const float* __restrict__ Betad,
    __nv_bfloat16* __restrict__ ThG, __nv_bfloat16* __restrict__ TlG,
    __nv_bfloat16* __restrict__ GhG, __nv_bfloat16* __restrict__ GlG)
{
    extern __shared__ char ags[];
    char* pKh = ags;               char* pKl = ags + AG_TILE;
    char* pQh = ags + 2 * AG_TILE; char* pQl = ags + 3 * AG_TILE;
    float* As = (float*)(ags + AG_AS);
    float* Tm = (float*)(ags + AG_TM);
    float* Ws = (float*)(ags + AG_WS);
    const uint32_t khB = smem_u32(pKh), klB = smem_u32(pKl);
    const uint32_t qhB = smem_u32(pQh), qlB = smem_u32(pQl);

    const int c = blockIdx.x, b = blockIdx.y;
    const int r0g = b * Tt + c * CH;
    const int tid = threadIdx.x, lane = tid & 31, wid = tid >> 5;
    const int mat = wid >> 2, mb = wid & 3;
    const int fr = lane >> 2, fc = 2 * (lane & 3);

    float cacc[8][4];
#pragma unroll
    for (int nb = 0; nb < 8; nb++)
#pragma unroll
        for (int e = 0; e < 4; e++) cacc[nb][e] = 0.f;

#pragma unroll 1
    for (int jt = 0; jt < 4; jt++) {
        if (jt) __syncthreads();
#pragma unroll
        for (int n = 0; n < 4; n++) {
            const int e = tid + n * 256;
            const int t = e >> 4, cc = e & 15;
            const uint32_t off = (uint32_t)t * 272u
                + ((uint32_t)(cc ^ ((t >> 3) & 1)) << 4);
            const size_t g = (size_t)(r0g + t) * Dd + jt * 128 + cc * 8;
            cp16(khB + off, KhG + g);
            cp16(klB + off, KlG + g);
            cp16(qhB + off, QhG + g);
            cp16(qlB + off, QlG + g);
        }
        asm volatile("cp.async.commit_group;");
        asm volatile("cp.async.wait_group 0;");
        __syncthreads();
#pragma unroll
        for (int p = 0; p < 3; p++) {
            const uint32_t aT = mat ? (p < 2 ? qhB : qlB) : (p < 2 ? khB : klB);
            const uint32_t bT = (p == 1) ? klB : khB;
#pragma unroll
            for (int k = 0; k < 8; k++) {
                uint32_t a[4];
                {
                    const int r = mb * 16 + (lane & 15);
                    const int cc = k * 2 + (lane >> 4);
                    ldsm_x4(a, aT + r * 272u + ((uint32_t)(cc ^ ((r >> 3) & 1)) << 4));
                }
#pragma unroll
                for (int nb4 = 0; nb4 < 4; nb4++) {
                    uint32_t bb[4];
                    const int r = nb4 * 16 + (lane & 7) + ((lane >> 4) << 3);
                    const int cc = k * 2 + ((lane >> 3) & 1);
                    ldsm_x4(bb, bT + r * 272u + ((uint32_t)(cc ^ ((r >> 3) & 1)) << 4));
                    mma_bf16(cacc[nb4 * 2 + 0], a, bb[0], bb[1]);
                    mma_bf16(cacc[nb4 * 2 + 1], a, bb[2], bb[3]);
                }
            }
        }
    }
    __syncthreads();

    const size_t gbase = ((size_t)(b * NCH) + c) * (CH * CH);
    const int t0r = mb * 16 + fr, t1r = t0r + 8;
    if (mat == 0) {
        const float bt0 = Betad[r0g + t0r], bt1 = Betad[r0g + t1r];
#pragma unroll
        for (int nb = 0; nb < 8; nb++) {
            const int j = nb * 8 + fc;
            float2 o0, o1;
            o0.x = (j     < t0r) ? bt0 * cacc[nb][0] : 0.f;
            o0.y = (j + 1 < t0r) ? bt0 * cacc[nb][1] : 0.f;
            o1.x = (j     < t1r) ? bt1 * cacc[nb][2] : 0.f;
            o1.y = (j + 1 < t1r) ? bt1 * cacc[nb][3] : 0.f;
            *(float2*)&As[t0r * 66 + j] = o0;
            *(float2*)&As[t1r * 66 + j] = o1;
        }
    } else {
        unsigned short* Gh = (unsigned short*)GhG;
        unsigned short* Gl = (unsigned short*)GlG;
#pragma unroll
        for (int nb = 0; nb < 8; nb++) {
            const int j = nb * 8 + fc;
            float v00 = (j     <= t0r) ? cacc[nb][0] : 0.f;
            float v01 = (j + 1 <= t0r) ? cacc[nb][1] : 0.f;
            float v10 = (j     <= t1r) ? cacc[nb][2] : 0.f;
            float v11 = (j + 1 <= t1r) ? cacc[nb][3] : 0.f;
            *(uint32_t*)&Gh[gbase + t0r * 64 + j] = pack2(v00, v01, true);
            *(uint32_t*)&Gl[gbase + t0r * 64 + j] = pack2(v00, v01, false);
            *(uint32_t*)&Gh[gbase + t1r * 64 + j] = pack2(v10, v11, true);
            *(uint32_t*)&Gl[gbase + t1r * 64 + j] = pack2(v10, v11, false);
        }
    }
    for (int e = tid; e < 64 * 66; e += 256) Tm[e] = 0.f;
    __syncthreads();

    if (wid < 4) {
        const int r = lane & 15;
        float Lr[16], val[16];
#pragma unroll
        for (int j = 0; j < 16; j++) Lr[j] = As[(wid * 16 + r) * 66 + wid * 16 + j];
#pragma unroll
        for (int cc = 0; cc < 16; cc++) val[cc] = (r == cc) ? 1.f : 0.f;
#pragma unroll
        for (int j = 0; j < 15; j++) {
#pragma unroll
            for (int cc = 0; cc < 16; cc++) {
                if (cc <= j) {
                    float tjc = __shfl_sync(0xffffffffu, val[cc], j);
                    if (r > j) val[cc] -= Lr[j] * tjc;
                }
            }
        }
        if (lane < 16) {
#pragma unroll
            for (int cc = 0; cc < 16; cc++)
                Tm[(wid * 16 + r) * 66 + wid * 16 + cc] = val[cc];
        }
    }
    __syncthreads();

    {
        const int oi[6] = {1, 2, 3, 2, 3, 3};
        const int oj[6] = {0, 0, 0, 1, 1, 2};
        const int r = tid >> 4, cc = tid & 15;
#pragma unroll 1
        for (int s6 = 0; s6 < 6; s6++) {
            const int bi = oi[s6], bj = oj[s6];
            float w = 0.f;
            for (int k = bj; k < bi; k++)
#pragma unroll
                for (int m = 0; m < 16; m++)
                    w += As[(bi * 16 + r) * 66 + k * 16 + m] *
                         Tm[(k * 16 + m) * 66 + bj * 16 + cc];
            Ws[r * 17 + cc] = w;
            __syncthreads();
            float t2 = 0.f;
#pragma unroll
            for (int m = 0; m < 16; m++)
                t2 += Tm[(bi * 16 + r) * 66 + bi * 16 + m] * Ws[m * 17 + cc];
            Tm[(bi * 16 + r) * 66 + bj * 16 + cc] = -t2;
            __syncthreads();
        }
    }

    {
        unsigned short* Th = (unsigned short*)ThG;
        unsigned short* Tl = (unsigned short*)TlG;
        for (int e = tid; e < 2048; e += 256) {
            const int t = e >> 5, j = (e & 31) * 2;
            *(uint32_t*)&Th[gbase + t * 64 + j] =
                pack2(Tm[t * 66 + j], Tm[t * 66 + j + 1], true);
            *(uint32_t*)&Tl[gbase + t * 64 + j] =
                pack2(Tm[t * 66 + j], Tm[t * 66 + j + 1], false);
        }
    }
}

// ---------------- chunked delta-rule scan: all-mma, frag reuse ----------------
__global__ __launch_bounds__(256) void scan_kernel(
    const __nv_bfloat16* __restrict__ KhG, const __nv_bfloat16* __restrict__ KlG,
    const __nv_bfloat16* __restrict__ QhG, const __nv_bfloat16* __restrict__ QlG,
    const __nv_bfloat16* __restrict__ ThG, const __nv_bfloat16* __restrict__ TlG,
    const __nv_bfloat16* __restrict__ GhG, const __nv_bfloat16* __restrict__ GlG,
    const float* __restrict__ Vd, const float* __restrict__ Betad,
    __nv_bfloat16* __restrict__ OhG, __nv_bfloat16* __restrict__ OlG)
{
    extern __shared__ char sraw[];
    float* S     = (float*)(sraw + OFF_S);
    float* QSm   = (float*)(sraw + OFF_QS);
    float* Vb    = (float*)(sraw + OFF_VB);
    float* betas = (float*)(sraw + OFF_BETA);
    char* pKh = sraw + OFF_KH;  char* pKl = sraw + OFF_KL;
    char* pQh = sraw + OFF_QH;  char* pQl = sraw + OFF_QL;
    char* pSh = sraw + OFF_SH;  char* pSl = sraw + OFF_SL;
    char* pUh = sraw + OFF_UH;  char* pUl = sraw + OFF_UL;
    char* pTh = sraw + OFF_TH;  char* pTl = sraw + OFF_TL;
    char* pGh = sraw + OFF_GH;  char* pGl = sraw + OFF_GL;
    const uint32_t khB = smem_u32(pKh), klB = smem_u32(pKl);
    const uint32_t qhB = smem_u32(pQh), qlB = smem_u32(pQl);
    const uint32_t shB = smem_u32(pSh), slB = smem_u32(pSl);
    const uint32_t uhB = smem_u32(pUh), ulB = smem_u32(pUl);
    const uint32_t thB = smem_u32(pTh), tlB = smem_u32(pTl);
    const uint32_t ghB = smem_u32(pGh), glB = smem_u32(pGl);

    const int b = blockIdx.y;
    const int i0 = blockIdx.x * DV;
    const int tid = threadIdx.x;
    const int lane = tid & 31, wid = tid >> 5;
    const int fr = lane >> 2, fc = 2 * (lane & 3);

    auto stu = [&](float v, int i, int t) {
        unsigned short h, l; split2(v, h, l);
        const uint32_t off = (uint32_t)i * 144u
            + ((uint32_t)((t >> 3) ^ ((i >> 3) & 1)) << 4) + (t & 7) * 2;
        *(unsigned short*)(pUh + off) = h;
        *(unsigned short*)(pUl + off) = l;
    };

    for (int e = tid; e < 32 * 520; e += 256) S[e] = 0.f;
    __syncthreads();

    for (int c = 0; c < NCH; c++) {
        const int r0g = b * Tt + c * CH;
        const size_t gbase = ((size_t)(b * NCH) + c) * (CH * CH);

        // issue T/G staging (group) and phase-A jt=0 K/Q staging (group)
#pragma unroll
        for (int n = 0; n < 2; n++) {
            const int e = tid + n * 256;
            const int r = e >> 3, cc = e & 7;
            const uint32_t off = (uint32_t)r * 144u
                + ((uint32_t)(cc ^ ((r >> 3) & 1)) << 4);
            const size_t g = gbase + r * 64 + cc * 8;
            cp16(thB + off, ThG + g);
            cp16(tlB + off, TlG + g);
            cp16(ghB + off, GhG + g);
            cp16(glB + off, GlG + g);
        }
        asm volatile("cp.async.commit_group;");
#pragma unroll
        for (int n = 0; n < 4; n++) {
            const int e = tid + n * 256;
            const int t = e >> 4, cc = e & 15;
            const uint32_t off = (uint32_t)t * 272u
                + ((uint32_t)(cc ^ ((t >> 3) & 1)) << 4);
            const size_t g = (size_t)(r0g + t) * Dd + cc * 8;   // jt = 0
            cp16(khB + off, KhG + g);
            cp16(klB + off, KlG + g);
            cp16(qhB + off, QhG + g);
            cp16(qlB + off, QlG + g);
        }
        asm volatile("cp.async.commit_group;");
        for (int e = tid; e < CH * DV; e += 256) {
            const int t = e >> 5, i = e & 31;
            Vb[t * 34 + i] = Vd[(size_t)(r0g + t) * Dd + i0 + i];
        }
        if (tid < 64) betas[tid] = Betad[r0g + tid];

        // ---- Phase A ----
        const int mat = wid >> 2;
        const int mb  = wid & 3;
        float cacc[4][4];
#pragma unroll
        for (int nb = 0; nb < 4; nb++)
#pragma unroll
            for (int e = 0; e < 4; e++) cacc[nb][e] = 0.f;

#pragma unroll 1
        for (int jt = 0; jt < 4; jt++) {
            if (jt > 0) {
#pragma unroll
                for (int n = 0; n < 4; n++) {
                    const int e = tid + n * 256;
                    const int t = e >> 4, cc = e & 15;
                    const uint32_t off = (uint32_t)t * 272u
                        + ((uint32_t)(cc ^ ((t >> 3) & 1)) << 4);
                    const size_t g = (size_t)(r0g + t) * Dd + jt * 128 + cc * 8;
                    cp16(khB + off, KhG + g);
                    cp16(klB + off, KlG + g);
                    cp16(qhB + off, QhG + g);
                    cp16(qlB + off, QlG + g);
                }
                asm volatile("cp.async.commit_group;");
            }
#pragma unroll
            for (int n = 0; n < 4; n++) {
                const int e = tid + n * 256;
                const int i = e >> 5, d4 = (e & 31) * 4;
                float4 v = *(const float4*)&S[i * 520 + jt * 128 + d4];
                ull hw, lw; split4(v, hw, lw);
                const uint32_t off = (uint32_t)i * 272u
                    + ((uint32_t)((d4 >> 3) ^ ((i >> 3) & 1)) << 4) + (d4 & 7) * 2;
                *(ull*)(pSh + off) = hw;
                *(ull*)(pSl + off) = lw;
            }
            asm volatile("cp.async.wait_group 0;");
            __syncthreads();
            const uint32_t aHi = mat ? qhB : khB;
            const uint32_t aLo = mat ? qlB : klB;
#pragma unroll
            for (int k = 0; k < 8; k++) {
                uint32_t aH[4], aL[4], bH0[4], bH1[4], bX0[4], bX1[4];
                const int ra = mb * 16 + (lane & 15);
                const int ca = k * 2 + (lane >> 4);
                const uint32_t aoff = ra * 272u + ((uint32_t)(ca ^ ((ra >> 3) & 1)) << 4);
                const int rb = (lane & 7) + ((lane >> 4) << 3);
                const int cb = k * 2 + ((lane >> 3) & 1);
                const uint32_t boff0 = rb * 272u + ((uint32_t)(cb ^ ((rb >> 3) & 1)) << 4);
                const int rb2 = rb + 16;
                const uint32_t boff1 = rb2 * 272u + ((uint32_t)(cb ^ ((rb2 >> 3) & 1)) << 4);
                ldsm_x4(aH, aHi + aoff);
                ldsm_x4(bH0, shB + boff0);
                ldsm_x4(bH1, shB + boff1);
                mma_bf16(cacc[0], aH, bH0[0], bH0[1]);
                mma_bf16(cacc[1], aH, bH0[2], bH0[3]);
                mma_bf16(cacc[2], aH, bH1[0], bH1[1]);
                mma_bf16(cacc[3], aH, bH1[2], bH1[3]);
                ldsm_x4(bX0, slB + boff0);
                ldsm_x4(bX1, slB + boff1);
                mma_bf16(cacc[0], aH, bX0[0], bX0[1]);
                mma_bf16(cacc[1], aH, bX0[2], bX0[3]);
                mma_bf16(cacc[2], aH, bX1[0], bX1[1]);
                mma_bf16(cacc[3], aH, bX1[2], bX1[3]);
                ldsm_x4(aL, aLo + aoff);
                mma_bf16(cacc[0], aL, bH0[0], bH0[1]);
                mma_bf16(cacc[1], aL, bH0[2], bH0[3]);
                mma_bf16(cacc[2], aL, bH1[0], bH1[1]);
                mma_bf16(cacc[3], aL, bH1[2], bH1[3]);
            }
            __syncthreads();
        }

        // epilogue: warps 0-3 write rhs splits directly to UH/UL; 4-7 -> QSm
        {
            const int t0r = mb * 16 + fr, t1r = t0r + 8;
            if (mat == 0) {
                const float b0v = betas[t0r], b1v = betas[t1r];
#pragma unroll
                for (int nb = 0; nb < 4; nb++) {
                    const int i = nb * 8 + fc;
                    float2 v0 = *(float2*)&Vb[t0r * 34 + i];
                    float2 v1 = *(float2*)&Vb[t1r * 34 + i];
                    stu(b0v * (v0.x - cacc[nb][0]), i,     t0r);
                    stu(b0v * (v0.y - cacc[nb][1]), i + 1, t0r);
                    stu(b1v * (v1.x - cacc[nb][2]), i,     t1r);
                    stu(b1v * (v1.y - cacc[nb][3]), i + 1, t1r);
                }
            } else {
#pragma unroll
                for (int nb = 0; nb < 4; nb++) {
                    const int i = nb * 8 + fc;
                    *(float2*)&QSm[t0r * 34 + i] = make_float2(cacc[nb][0], cacc[nb][1]);
                    *(float2*)&QSm[t1r * 34 + i] = make_float2(cacc[nb][2], cacc[nb][3]);
                }
            }
        }
        __syncthreads();

        // Phase B': U = T @ rhs (frag reuse); epilogue writes U splits in place
        {
            const int mb2 = wid >> 1, nh = wid & 1;
            float du[2][4];
#pragma unroll
            for (int n8 = 0; n8 < 2; n8++)
#pragma unroll
                for (int e = 0; e < 4; e++) du[n8][e] = 0.f;
#pragma unroll
            for (int k = 0; k < 4; k++) {
                uint32_t aH[4], aL[4], bH[4], bX[4];
                const int ra = mb2 * 16 + (lane & 15);
                const int ca = k * 2 + (lane >> 4);
                const uint32_t aoff = ra * 144u + ((uint32_t)(ca ^ ((ra >> 3) & 1)) << 4);
                const int rb = nh * 16 + (lane & 7) + ((lane >> 4) << 3);
                const int cb = k * 2 + ((lane >> 3) & 1);
                const uint32_t boff = rb * 144u + ((uint32_t)(cb ^ ((rb >> 3) & 1)) << 4);
                ldsm_x4(aH, thB + aoff);
                ldsm_x4(bH, uhB + boff);
                mma_bf16(du[0], aH, bH[0], bH[1]);
                mma_bf16(du[1], aH, bH[2], bH[3]);
                ldsm_x4(bX, ulB + boff);
                mma_bf16(du[0], aH, bX[0], bX[1]);
                mma_bf16(du[1], aH, bX[2], bX[3]);
                ldsm_x4(aL, tlB + aoff);
                mma_bf16(du[0], aL, bH[0], bH[1]);
                mma_bf16(du[1], aL, bH[2], bH[3]);
            }
            __syncthreads();   // rhs reads complete before overwrite
            const int t0r = mb2 * 16 + fr, t1r = t0r + 8;
#pragma unroll
            for (int n8 = 0; n8 < 2; n8++) {
                const int i = nh * 16 + n8 * 8 + fc;
                stu(du[n8][0], i,     t0r);
                stu(du[n8][1], i + 1, t0r);
                stu(du[n8][2], i,     t1r);
                stu(du[n8][3], i + 1, t1r);
            }
        }
        __syncthreads();

        // issue phase-D jt=0 K staging into K slot (overlaps phase C')
#pragma unroll
        for (int n = 0; n < 4; n++) {
            const int e = tid + n * 256;
            const int t = e >> 4, cc = e & 15;
            const uint32_t off = (uint32_t)t * 272u
                + ((uint32_t)(cc ^ ((t >> 3) & 1)) << 4);
            const size_t g = (size_t)(r0g + t) * Dd + cc * 8;    // jt = 0
            cp16(khB + off, KhG + g);
            cp16(klB + off, KlG + g);
        }
        asm volatile("cp.async.commit_group;");

        // Phase C': O = QS + G @ U (frag reuse, split bf16 output)
        {
            const int mb2 = wid >> 1, nh = wid & 1;
            const int t0r = mb2 * 16 + fr, t1r = t0r + 8;
            float du[2][4];
#pragma unroll
            for (int n8 = 0; n8 < 2; n8++) {
                const int i = nh * 16 + n8 * 8 + fc;
                float2 q0 = *(float2*)&QSm[t0r * 34 + i];
                float2 q1 = *(float2*)&QSm[t1r * 34 + i];
                du[n8][0] = q0.x; du[n8][1] = q0.y;
                du[n8][2] = q1.x; du[n8][3] = q1.y;
            }
#pragma unroll
            for (int k = 0; k < 4; k++) {
                uint32_t aH[4], aL[4], bH[4], bX[4];
                const int ra = mb2 * 16 + (lane & 15);
                const int ca = k * 2 + (lane >> 4);
                const uint32_t aoff = ra * 144u + ((uint32_t)(ca ^ ((ra >> 3) & 1)) << 4);
                const int rb = nh * 16 + (lane & 7) + ((lane >> 4) << 3);
                const int cb = k * 2 + ((lane >> 3) & 1);
                const uint32_t boff = rb * 144u + ((uint32_t)(cb ^ ((rb >> 3) & 1)) << 4);
                ldsm_x4(aH, ghB + aoff);
                ldsm_x4(bH, uhB + boff);
                mma_bf16(du[0], aH, bH[0], bH[1]);
                mma_bf16(du[1], aH, bH[2], bH[3]);
                ldsm_x4(bX, ulB + boff);
                mma_bf16(du[0], aH, bX[0], bX[1]);
                mma_bf16(du[1], aH, bX[2], bX[3]);
                ldsm_x4(aL, glB + aoff);
                mma_bf16(du[0], aL, bH[0], bH[1]);
                mma_bf16(du[1], aL, bH[2], bH[3]);
            }
            unsigned short* oh = (unsigned short*)OhG;
            unsigned short* ol = (unsigned short*)OlG;
#pragma unroll
            for (int n8 = 0; n8 < 2; n8++) {
                const int i = nh * 16 + n8 * 8 + fc;
                const size_t g0 = (size_t)(r0g + t0r) * Dd + i0 + i;
                const size_t g1 = (size_t)(r0g + t1r) * Dd + i0 + i;
                *(uint32_t*)&oh[g0] = pack2(du[n8][0], du[n8][1], true);
                *(uint32_t*)&ol[g0] = pack2(du[n8][0], du[n8][1], false);
                *(uint32_t*)&oh[g1] = pack2(du[n8][2], du[n8][3], true);
                *(uint32_t*)&ol[g1] = pack2(du[n8][2], du[n8][3], false);
            }
        }

        // Phase D: S += U^T @ K  (double-buffered staging K<->Q, frag reuse)
#pragma unroll 1
        for (int jt = 0; jt < 4; jt++) {
            const uint32_t curH = (jt & 1) ? qhB : khB;
            const uint32_t curL = (jt & 1) ? qlB : klB;
            if (jt + 1 < 4) {
                const uint32_t nxtH = ((jt + 1) & 1) ? qhB : khB;
                const uint32_t nxtL = ((jt + 1) & 1) ? qlB : klB;
#pragma unroll
                for (int n = 0; n < 4; n++) {
                    const int e = tid + n * 256;
                    const int t = e >> 4, cc = e & 15;
                    const uint32_t off = (uint32_t)t * 272u
                        + ((uint32_t)(cc ^ ((t >> 3) & 1)) << 4);
                    const size_t g = (size_t)(r0g + t) * Dd + (jt + 1) * 128 + cc * 8;
                    cp16(nxtH + off, KhG + g);
                    cp16(nxtL + off, KlG + g);
                }
                asm volatile("cp.async.commit_group;");
                asm volatile("cp.async.wait_group 1;");
            } else {
                asm volatile("cp.async.wait_group 0;");
            }
            __syncthreads();

            float cf[2][2][4];
            const int dbase = jt * 128 + wid * 16;
#pragma unroll
            for (int mi = 0; mi < 2; mi++)
#pragma unroll
                for (int n8 = 0; n8 < 2; n8++) {
                    const int i0r = mi * 16 + fr;
                    const int col = dbase + n8 * 8 + fc;
                    float2 x0 = *(float2*)&S[i0r * 520 + col];
                    float2 x1 = *(float2*)&S[(i0r + 8) * 520 + col];
                    cf[mi][n8][0] = x0.x; cf[mi][n8][1] = x0.y;
                    cf[mi][n8][2] = x1.x; cf[mi][n8][3] = x1.y;
                }
#pragma unroll
            for (int k = 0; k < 4; k++) {
                uint32_t aH0[4], aH1[4], aL0[4], aL1[4], bH[4], bX[4];
                const int r = lane & 15;
                const int ca = k * 2 + (lane >> 4);
                const uint32_t aoff0 = r * 144u + ((uint32_t)(ca ^ ((r >> 3) & 1)) << 4);
                const int r2 = 16 + (lane & 15);
                const uint32_t aoff1 = r2 * 144u + ((uint32_t)(ca ^ ((r2 >> 3) & 1)) << 4);
                const int tr = k * 16 + (lane & 15);
                const int cb = wid * 2 + (lane >> 4);
                const uint32_t boff = tr * 272u + ((uint32_t)(cb ^ ((tr >> 3) & 1)) << 4);
                ldsm_x4(aH0, uhB + aoff0);
                ldsm_x4(aH1, uhB + aoff1);
                ldsm_x4t(bH, curH + boff);
                mma_bf16(cf[0][0], aH0, bH[0], bH[1]);
                mma_bf16(cf[0][1], aH0, bH[2], bH[3]);
                mma_bf16(cf[1][0], aH1, bH[0], bH[1]);
                mma_bf16(cf[1][1], aH1, bH[2], bH[3]);
                ldsm_x4t(bX, curL + boff);
                mma_bf16(cf[0][0], aH0, bX[0], bX[1]);
                mma_bf16(cf[0][1], aH0, bX[2], bX[3]);
                mma_bf16(cf[1][0], aH1, bX[0], bX[1]);
                mma_bf16(cf[1][1], aH1, bX[2], bX[3]);
                ldsm_x4(aL0, ulB + aoff0);
                ldsm_x4(aL1, ulB + aoff1);
                mma_bf16(cf[0][0], aL0, bH[0], bH[1]);
                mma_bf16(cf[0][1], aL0, bH[2], bH[3]);
                mma_bf16(cf[1][0], aL1, bH[0], bH[1]);
                mma_bf16(cf[1][1], aL1, bH[2], bH[3]);
            }
#pragma unroll
            for (int mi = 0; mi < 2; mi++)
#pragma unroll
                for (int n8 = 0; n8 < 2; n8++) {
                    const int i0r = mi * 16 + fr;
                    const int col = dbase + n8 * 8 + fc;
                    *(float2*)&S[i0r * 520 + col] =
                        make_float2(cf[mi][n8][0], cf[mi][n8][1]);
                    *(float2*)&S[(i0r + 8) * 520 + col] =
                        make_float2(cf[mi][n8][2], cf[mi][n8][3]);
                }
            __syncthreads();
        }
    }
}

extern "C" void kernel_launch(void* const* d_in, const int* in_sizes, int n_in,
                              void* d_out, int out_size)
{
    const float* x     = (const float*)d_in[0];
    const float* Wq    = (const float*)d_in[1];
    const float* bq    = (const float*)d_in[2];
    const float* Wk    = (const float*)d_in[3];
    const float* bk    = (const float*)d_in[4];
    const float* Wv    = (const float*)d_in[5];
    const float* bv    = (const float*)d_in[6];
    const float* Wbeta = (const float*)d_in[7];
    const float* bbeta = (const float*)d_in[8];
    const float* Wo    = (const float*)d_in[9];
    const float* bo    = (const float*)d_in[10];
    float* out = (float*)d_out;

    float *pK, *pV, *pBeta;
    cudaGetSymbolAddress((void**)&pK, g_K);
    cudaGetSymbolAddress((void**)&pV, g_V);
    cudaGetSymbolAddress((void**)&pBeta, g_Beta);

    __nv_bfloat16 *pxh, *pxl, *poh, *pol, *pkh, *pkl, *pqh, *pql;
    __nv_bfloat16 *pTh, *pTl, *pGh, *pGl;
    __nv_bfloat16 *pwqh, *pwql, *pwkh, *pwkl, *pwvh, *pwvl, *pwoh, *pwol;
    cudaGetSymbolAddress((void**)&pxh, g_xh);
    cudaGetSymbolAddress((void**)&pxl, g_xl);
    cudaGetSymbolAddress((void**)&poh, g_oh);
    cudaGetSymbolAddress((void**)&pol, g_ol);
    cudaGetSymbolAddress((void**)&pkh, g_kh);
    cudaGetSymbolAddress((void**)&pkl, g_kl);
    cudaGetSymbolAddress((void**)&pqh, g_qh);
    cudaGetSymbolAddress((void**)&pql, g_ql);
    cudaGetSymbolAddress((void**)&pTh, g_Th);
    cudaGetSymbolAddress((void**)&pTl, g_Tl);
    cudaGetSymbolAddress((void**)&pGh, g_Gh);
    cudaGetSymbolAddress((void**)&pGl, g_Gl);
    cudaGetSymbolAddress((void**)&pwqh, g_wqh);
    cudaGetSymbolAddress((void**)&pwql, g_wql);
    cudaGetSymbolAddress((void**)&pwkh, g_wkh);
    cudaGetSymbolAddress((void**)&pwkl, g_wkl);
    cudaGetSymbolAddress((void**)&pwvh, g_wvh);
    cudaGetSymbolAddress((void**)&pwvl, g_wvl);
    cudaGetSymbolAddress((void**)&pwoh, g_woh);
    cudaGetSymbolAddress((void**)&pwol, g_wol);

    cudaFuncSetAttribute(scan_kernel,
                         cudaFuncAttributeMaxDynamicSharedMemorySize, SCAN_SMEM);
    cudaFuncSetAttribute(tgemm_mma_kernel,
                         cudaFuncAttributeMaxDynamicSharedMemorySize, TG_SMEM);
    cudaFuncSetAttribute(tgemm_qkv_kernel,
                         cudaFuncAttributeMaxDynamicSharedMemorySize, TG_SMEM);
    cudaFuncSetAttribute(chunk_ag_mma_kernel,
                         cudaFuncAttributeMaxDynamicSharedMemorySize, AG_SMEM);

    const int nx4 = BT * Dd / 4;
    const int nw4 = Dd * Dd / 4;
    split_kernel<<<(nx4 + 255) / 256, 256>>>(x, pxh, pxl, nx4);
    split_w_kernel<<<dim3((nw4 + 255) / 256, 4), 256>>>(
        Wq, Wk, Wv, Wo, pwqh, pwql, pwkh, pwkl, pwvh, pwvl, pwoh, pwol, nw4);

    tgemm_qkv_kernel<<<dim3(12, BT / 128), 256, TG_SMEM>>>(
        pxh, pxl, pwqh, pwql, pwkh, pwkl, pwvh, pwvl, bq, bk, bv,
        pqh, pql, pK, pV);

    norm_beta_kernel<<<BT, 128>>>(pK, Wbeta, bbeta, pBeta, pkh, pkl);

    chunk_ag_mma_kernel<<<dim3(NCH, Bb), 256, AG_SMEM>>>(
        pkh, pkl, pqh, pql, pBeta, pTh, pTl, pGh, pGl);

    scan_kernel<<<dim3(NVT, Bb), 256, SCAN_SMEM>>>(
        pkh, pkl, pqh, pql, pTh, pTl, pGh, pGl, pV, pBeta, poh, pol);

    tgemm_mma_kernel<<<dim3(4, BT / 128), 256, TG_SMEM>>>(
        poh, pol, pwoh, pwol, bo, out);
}

// round 17
// speedup vs baseline: 1.0856x; 1.0489x over previous
#include <cuda_runtime.h>
#include <cuda_bf16.h>
#include <math.h>
#include <stdint.h>

namespace {
constexpr int Bb  = 8;
constexpr int Tt  = 2048;
constexpr int Dd  = 512;
constexpr int BT  = Bb * Tt;
constexpr int CH  = 64;
constexpr int NCH = Tt / CH;   // 32
constexpr int DV  = 32;
constexpr int NVT = Dd / DV;   // 16

// ---- scan smem layout (byte offsets; S now lives in registers) ----
constexpr int OFF_QS   = 0;              // float [64][34]   8704
constexpr int OFF_VB   = 8704;           // float [64][34]   8704
constexpr int OFF_BETA = 17408;          // float [64]        256
constexpr int OFF_KH   = 17664;          // bf16 [64][136]  17408
constexpr int OFF_KL   = 35072;
constexpr int OFF_QH   = 52480;
constexpr int OFF_QL   = 69888;
constexpr int OFF_SH   = 87296;          // bf16 [32][136]   8704
constexpr int OFF_SL   = 96000;
constexpr int OFF_UH   = 104704;         // bf16 [32][72]    4608
constexpr int OFF_UL   = 109312;
constexpr int OFF_TH   = 113920;         // bf16 [64][72]    9216
constexpr int OFF_TL   = 123136;
constexpr int OFF_GH   = 132352;
constexpr int OFF_GL   = 141568;
constexpr int SCAN_SMEM = 150784;

// tgemm: 2 slots x (Ah|Al|Bh|Bl) each 128x40 halves = 10240 B
constexpr int TG_TILE  = 10240;
constexpr int TG_SLOT  = 4 * TG_TILE;
constexpr int TG_SMEM  = 2 * TG_SLOT;          // 81920 -> 2 CTAs/SM

// chunk_ag smem
constexpr int AG_TILE  = 17408;
constexpr int AG_AS    = 4 * AG_TILE;
constexpr int AG_TM    = AG_AS + 64 * 66 * 4;
constexpr int AG_WS    = AG_TM + 64 * 66 * 4;
constexpr int AG_SMEM  = AG_WS + 16 * 17 * 4;  // 104512
}

using ull = unsigned long long;

// ---------------- device scratch ----------------
__device__ float g_K[BT * Dd];
__device__ float g_V[BT * Dd];
__device__ float g_Beta[BT];
__device__ __nv_bfloat16 g_xh[BT * Dd];
__device__ __nv_bfloat16 g_xl[BT * Dd];
__device__ __nv_bfloat16 g_oh[BT * Dd];
__device__ __nv_bfloat16 g_ol[BT * Dd];
__device__ __nv_bfloat16 g_kh[BT * Dd];
__device__ __nv_bfloat16 g_kl[BT * Dd];
__device__ __nv_bfloat16 g_qh[BT * Dd];
__device__ __nv_bfloat16 g_ql[BT * Dd];
__device__ __nv_bfloat16 g_Th[Bb * NCH * CH * CH];
__device__ __nv_bfloat16 g_Tl[Bb * NCH * CH * CH];
__device__ __nv_bfloat16 g_Gh[Bb * NCH * CH * CH];
__device__ __nv_bfloat16 g_Gl[Bb * NCH * CH * CH];
__device__ __nv_bfloat16 g_wqh[Dd * Dd];
__device__ __nv_bfloat16 g_wql[Dd * Dd];
__device__ __nv_bfloat16 g_wkh[Dd * Dd];
__device__ __nv_bfloat16 g_wkl[Dd * Dd];
__device__ __nv_bfloat16 g_wvh[Dd * Dd];
__device__ __nv_bfloat16 g_wvl[Dd * Dd];
__device__ __nv_bfloat16 g_woh[Dd * Dd];
__device__ __nv_bfloat16 g_wol[Dd * Dd];

__device__ __forceinline__ uint32_t smem_u32(const void* p) {
    uint32_t a;
    asm("{ .reg .u64 t; cvta.to.shared.u64 t,%1; cvt.u32.u64 %0,t; }" : "=r"(a) : "l"(p));
    return a;
}
__device__ __forceinline__ void ldsm_x4(uint32_t* r, uint32_t addr) {
    asm volatile("ldmatrix.sync.aligned.m8n8.x4.shared.b16 {%0,%1,%2,%3}, [%4];"
                 : "=r"(r[0]), "=r"(r[1]), "=r"(r[2]), "=r"(r[3]) : "r"(addr));
}
__device__ __forceinline__ void ldsm_x4t(uint32_t* r, uint32_t addr) {
    asm volatile("ldmatrix.sync.aligned.m8n8.x4.trans.shared.b16 {%0,%1,%2,%3}, [%4];"
                 : "=r"(r[0]), "=r"(r[1]), "=r"(r[2]), "=r"(r[3]) : "r"(addr));
}
__device__ __forceinline__ void mma_bf16(float* d, const uint32_t* a,
                                         uint32_t b0, uint32_t b1) {
    asm volatile(
        "mma.sync.aligned.m16n8k16.row.col.f32.bf16.bf16.f32 "
        "{%0,%1,%2,%3}, {%4,%5,%6,%7}, {%8,%9}, {%0,%1,%2,%3};"
        : "+f"(d[0]), "+f"(d[1]), "+f"(d[2]), "+f"(d[3])
        : "r"(a[0]), "r"(a[1]), "r"(a[2]), "r"(a[3]), "r"(b0), "r"(b1));
}
__device__ __forceinline__ void cp16(uint32_t dst, const void* src) {
    asm volatile("cp.async.ca.shared.global [%0], [%1], 16;" :: "r"(dst), "l"(src));
}
__device__ __forceinline__ void split2(float x, unsigned short& h, unsigned short& l) {
    __nv_bfloat16 hh = __float2bfloat16(x);
    __nv_bfloat16 ll = __float2bfloat16(x - __bfloat162float(hh));
    h = __bfloat16_as_ushort(hh); l = __bfloat16_as_ushort(ll);
}
__device__ __forceinline__ void split4(float4 v, ull& h, ull& l) {
    unsigned short h0, h1, h2, h3, l0, l1, l2, l3;
    split2(v.x, h0, l0); split2(v.y, h1, l1);
    split2(v.z, h2, l2); split2(v.w, h3, l3);
    h = (ull)h0 | ((ull)h1 << 16) | ((ull)h2 << 32) | ((ull)h3 << 48);
    l = (ull)l0 | ((ull)l1 << 16) | ((ull)l2 << 32) | ((ull)l3 << 48);
}
__device__ __forceinline__ uint32_t pack2(float a, float b, bool hi) {
    unsigned short ha, la, hb, lb;
    split2(a, ha, la); split2(b, hb, lb);
    return hi ? ((uint32_t)ha | ((uint32_t)hb << 16))
              : ((uint32_t)la | ((uint32_t)lb << 16));
}

// ---------------- split fp32 -> bf16 hi/lo ----------------
__global__ __launch_bounds__(256) void split_kernel(
    const float* __restrict__ x, __nv_bfloat16* __restrict__ h,
    __nv_bfloat16* __restrict__ l, int n4)
{
    int i = blockIdx.x * 256 + threadIdx.x;
    if (i >= n4) return;
    float4 v = ((const float4*)x)[i];
    ull hw, lw; split4(v, hw, lw);
    ((ull*)h)[i] = hw;
    ((ull*)l)[i] = lw;
}

// ---------------- merged weight split ----------------
__global__ __launch_bounds__(256) void split_w_kernel(
    const float* __restrict__ Wq, const float* __restrict__ Wk,
    const float* __restrict__ Wv, const float* __restrict__ Wo,
    __nv_bfloat16* __restrict__ qh, __nv_bfloat16* __restrict__ ql,
    __nv_bfloat16* __restrict__ kh, __nv_bfloat16* __restrict__ kl,
    __nv_bfloat16* __restrict__ vh, __nv_bfloat16* __restrict__ vl,
    __nv_bfloat16* __restrict__ oh, __nv_bfloat16* __restrict__ ol,
    int n4)
{
    int i = blockIdx.x * 256 + threadIdx.x;
    if (i >= n4) return;
    const int w = blockIdx.y;
    const float* src = (w == 0) ? Wq : (w == 1) ? Wk : (w == 2) ? Wv : Wo;
    __nv_bfloat16* h = (w == 0) ? qh : (w == 1) ? kh : (w == 2) ? vh : oh;
    __nv_bfloat16* l = (w == 0) ? ql : (w == 1) ? kl : (w == 2) ? vl : ol;
    float4 v = ((const float4*)src)[i];
    ull hw, lw; split4(v, hw, lw);
    ((ull*)h)[i] = hw;
    ((ull*)l)[i] = lw;
}

// ---------------- HMMA split-bf16 GEMM body (2-slot cp.async, frag reuse) ----
__device__ __forceinline__ void tgemm_body(
    const __nv_bfloat16* __restrict__ Ah, const __nv_bfloat16* __restrict__ Al,
    const __nv_bfloat16* __restrict__ Bh, const __nv_bfloat16* __restrict__ Bl,
    const float* __restrict__ bias, float* __restrict__ C,
    __nv_bfloat16* __restrict__ Ch, __nv_bfloat16* __restrict__ Cl,
    int bm, int bn, char* tgs)
{
    const uint32_t sBase = smem_u32(tgs);
    const int tid = threadIdx.x, lane = tid & 31, wid = tid >> 5;
    const int wm = wid & 1, wn = wid >> 1;

    float d[4][4][4];
#pragma unroll
    for (int mt = 0; mt < 4; mt++)
#pragma unroll
        for (int nt = 0; nt < 4; nt++)
#pragma unroll
            for (int e = 0; e < 4; e++) d[mt][nt][e] = 0.f;

    uint32_t a_rel[4], b_rel[2];
    {
        const int ar = lane & 15, akoff = (lane >> 4) * 8;
#pragma unroll
        for (int mt = 0; mt < 4; mt++)
            a_rel[mt] = ((wm * 64 + mt * 16 + ar) * 40 + akoff) * 2;
        const int nrow = wn * 32 + ((lane >> 4) << 3) + (lane & 7);
        const int khalf = (lane >> 3) & 1;
#pragma unroll
        for (int np = 0; np < 2; np++)
            b_rel[np] = ((nrow + np * 16) * 40 + khalf * 8) * 2;
    }

    const int srow0 = tid >> 2,         sc0 = tid & 3;
    const int srow1 = (tid + 256) >> 2, sc1 = (tid + 256) & 3;
    const uint32_t st0 = srow0 * 80 + sc0 * 16;
    const uint32_t st1 = srow1 * 80 + sc1 * 16;

    auto issue = [&](int kt, int slot) {
        const uint32_t b0 = sBase + slot * TG_SLOT;
        const size_t ga0 = (size_t)(bm + srow0) * Dd + kt * 32 + sc0 * 8;
        const size_t ga1 = (size_t)(bm + srow1) * Dd + kt * 32 + sc1 * 8;
        const size_t gb0 = (size_t)(bn + srow0) * Dd + kt * 32 + sc0 * 8;
        const size_t gb1 = (size_t)(bn + srow1) * Dd + kt * 32 + sc1 * 8;
        cp16(b0 + st0,               Ah + ga0);
        cp16(b0 + st1,               Ah + ga1);
        cp16(b0 + TG_TILE + st0,     Al + ga0);
        cp16(b0 + TG_TILE + st1,     Al + ga1);
        cp16(b0 + 2 * TG_TILE + st0, Bh + gb0);
        cp16(b0 + 2 * TG_TILE + st1, Bh + gb1);
        cp16(b0 + 3 * TG_TILE + st0, Bl + gb0);
        cp16(b0 + 3 * TG_TILE + st1, Bl + gb1);
        asm volatile("cp.async.commit_group;");
    };

    issue(0, 0);
#pragma unroll 1
    for (int s = 0; s < 16; s++) {
        if (s + 1 < 16) {
            issue(s + 1, (s + 1) & 1);
            asm volatile("cp.async.wait_group 1;");
        } else {
            asm volatile("cp.async.wait_group 0;");
        }
        __syncthreads();
        const uint32_t slotB = sBase + (s & 1) * TG_SLOT;
#pragma unroll
        for (int ks = 0; ks < 2; ks++) {
            uint32_t aH[4][4], aL[4][4], bH[2][4], bX[2][4];
#pragma unroll
            for (int mt = 0; mt < 4; mt++)
                ldsm_x4(aH[mt], slotB + a_rel[mt] + ks * 32);
#pragma unroll
            for (int np = 0; np < 2; np++)
                ldsm_x4(bH[np], slotB + 2 * TG_TILE + b_rel[np] + ks * 32);
#pragma unroll
            for (int mt = 0; mt < 4; mt++)
#pragma unroll
                for (int nt = 0; nt < 4; nt++)
                    mma_bf16(d[mt][nt], aH[mt],
                             bH[nt >> 1][(nt & 1) * 2], bH[nt >> 1][(nt & 1) * 2 + 1]);
#pragma unroll
            for (int np = 0; np < 2; np++)
                ldsm_x4(bX[np], slotB + 3 * TG_TILE + b_rel[np] + ks * 32);
#pragma unroll
            for (int mt = 0; mt < 4; mt++)
#pragma unroll
                for (int nt = 0; nt < 4; nt++)
                    mma_bf16(d[mt][nt], aH[mt],
                             bX[nt >> 1][(nt & 1) * 2], bX[nt >> 1][(nt & 1) * 2 + 1]);
#pragma unroll
            for (int mt = 0; mt < 4; mt++)
                ldsm_x4(aL[mt], slotB + TG_TILE + a_rel[mt] + ks * 32);
#pragma unroll
            for (int mt = 0; mt < 4; mt++)
#pragma unroll
                for (int nt = 0; nt < 4; nt++)
                    mma_bf16(d[mt][nt], aL[mt],
                             bH[nt >> 1][(nt & 1) * 2], bH[nt >> 1][(nt & 1) * 2 + 1]);
        }
        __syncthreads();
    }

#pragma unroll
    for (int mt = 0; mt < 4; mt++) {
        const int r0 = bm + wm * 64 + mt * 16 + (lane >> 2);
#pragma unroll
        for (int nt = 0; nt < 4; nt++) {
            const int c0 = bn + wn * 32 + nt * 8 + (lane & 3) * 2;
            const float b0 = bias[c0], b1 = bias[c0 + 1];
            const float o00 = d[mt][nt][0] + b0, o01 = d[mt][nt][1] + b1;
            const float o10 = d[mt][nt][2] + b0, o11 = d[mt][nt][3] + b1;
            if (C) {
                *(float2*)&C[(size_t)r0 * Dd + c0] = make_float2(o00, o01);
                *(float2*)&C[(size_t)(r0 + 8) * Dd + c0] = make_float2(o10, o11);
            } else {
                unsigned short* ch = (unsigned short*)Ch;
                unsigned short* cl = (unsigned short*)Cl;
                *(uint32_t*)&ch[(size_t)r0 * Dd + c0] = pack2(o00, o01, true);
                *(uint32_t*)&cl[(size_t)r0 * Dd + c0] = pack2(o00, o01, false);
                *(uint32_t*)&ch[(size_t)(r0 + 8) * Dd + c0] = pack2(o10, o11, true);
                *(uint32_t*)&cl[(size_t)(r0 + 8) * Dd + c0] = pack2(o10, o11, false);
            }
        }
    }
}

__global__ __launch_bounds__(256, 2) void tgemm_mma_kernel(
    const __nv_bfloat16* __restrict__ Ah, const __nv_bfloat16* __restrict__ Al,
    const __nv_bfloat16* __restrict__ Bh, const __nv_bfloat16* __restrict__ Bl,
    const float* __restrict__ bias, float* __restrict__ C)
{
    extern __shared__ char tgs[];
    tgemm_body(Ah, Al, Bh, Bl, bias, C, nullptr, nullptr,
               blockIdx.y * 128, blockIdx.x * 128, tgs);
}

__global__ __launch_bounds__(256, 2) void tgemm_qkv_kernel(
    const __nv_bfloat16* __restrict__ Ah, const __nv_bfloat16* __restrict__ Al,
    const __nv_bfloat16* __restrict__ Bqh, const __nv_bfloat16* __restrict__ Bql,
    const __nv_bfloat16* __restrict__ Bkh, const __nv_bfloat16* __restrict__ Bkl,
    const __nv_bfloat16* __restrict__ Bvh, const __nv_bfloat16* __restrict__ Bvl,
    const float* __restrict__ bq, const float* __restrict__ bk,
    const float* __restrict__ bv,
    __nv_bfloat16* __restrict__ Qh, __nv_bfloat16* __restrict__ Ql,
    float* __restrict__ Ck, float* __restrict__ Cv)
{
    extern __shared__ char tgs[];
    const int gsel = blockIdx.x >> 2;
    const int bn = (blockIdx.x & 3) * 128;
    const __nv_bfloat16* Bh = (gsel == 0) ? Bqh : (gsel == 1) ? Bkh : Bvh;
    const __nv_bfloat16* Bl = (gsel == 0) ? Bql : (gsel == 1) ? Bkl : Bvl;
    const float* bias = (gsel == 0) ? bq : (gsel == 1) ? bk : bv;
    float* C = (gsel == 0) ? nullptr : (gsel == 1) ? Ck : Cv;
    tgemm_body(Ah, Al, Bh, Bl, bias, C,
               (gsel == 0) ? Qh : nullptr, (gsel == 0) ? Ql : nullptr,
               blockIdx.y * 128, bn, tgs);
}

// ---------------- l2norm + beta -> split K directly ----------------
__global__ __launch_bounds__(128) void norm_beta_kernel(
    const float* __restrict__ Kd, const float* __restrict__ wb,
    const float* __restrict__ bb, float* __restrict__ Beta,
    __nv_bfloat16* __restrict__ Kh, __nv_bfloat16* __restrict__ Kl)
{
    const int row = blockIdx.x, tid = threadIdx.x;
    float4 v = ((const float4*)(Kd + (size_t)row * Dd))[tid];
    float ss = v.x * v.x + v.y * v.y + v.z * v.z + v.w * v.w;
#pragma unroll
    for (int o = 16; o; o >>= 1) ss += __shfl_xor_sync(0xffffffffu, ss, o);
    __shared__ float red1[4];
    if ((tid & 31) == 0) red1[tid >> 5] = ss;
    __syncthreads();
    const float inv = 1.0f / fmaxf(sqrtf(red1[0] + red1[1] + red1[2] + red1[3]), 1e-12f);
    float4 w = ((const float4*)wb)[tid];
    float bd = v.x * w.x + v.y * w.y + v.z * w.z + v.w * w.w;
#pragma unroll
    for (int o = 16; o; o >>= 1) bd += __shfl_xor_sync(0xffffffffu, bd, o);
    __shared__ float red2[4];
    if ((tid & 31) == 0) red2[tid >> 5] = bd;
    __syncthreads();
    v.x *= inv; v.y *= inv; v.z *= inv; v.w *= inv;
    ull hw, lw; split4(v, hw, lw);
    ((ull*)(Kh + (size_t)row * Dd))[tid] = hw;
    ((ull*)(Kl + (size_t)row * Dd))[tid] = lw;
    if (tid == 0) {
        const float z = (red2[0] + red2[1] + red2[2] + red2[3]) * inv + bb[0];
        Beta[row] = 1.0f / (1.0f + expf(-z));
    }
}

// ---------------- chunk_ag: A,G via mma + T = (I+A)^-1 ----------------
__global__ __launch_bounds__(256) void chunk_ag_mma_kernel(
    const __nv_bfloat16* __restrict__ KhG, const __nv_bfloat16* __restrict__ KlG,
    const __nv_bfloat16* __restrict__ QhG, const __nv_bfloat16* __restrict__ QlG,
    const float* __restrict__ Betad,
    __nv_bfloat16* __restrict__ ThG, __nv_bfloat16* __restrict__ TlG,
    __nv_bfloat16* __restrict__ GhG, __nv_bfloat16* __restrict__ GlG)
{
    extern __shared__ char ags[];
    char* pKh = ags;               char* pKl = ags + AG_TILE;
    char* pQh = ags + 2 * AG_TILE; char* pQl = ags + 3 * AG_TILE;
    float* As = (float*)(ags + AG_AS);
    float* Tm = (float*)(ags + AG_TM);
    float* Ws = (float*)(ags + AG_WS);
    const uint32_t khB = smem_u32(pKh), klB = smem_u32(pKl);
    const uint32_t qhB = smem_u32(pQh), qlB = smem_u32(pQl);

    const int c = blockIdx.x, b = blockIdx.y;
    const int r0g = b * Tt + c * CH;
    const int tid = threadIdx.x, lane = tid & 31, wid = tid >> 5;
    const int mat = wid >> 2, mb = wid & 3;
    const int fr = lane >> 2, fc = 2 * (lane & 3);

    float cacc[8][4];
#pragma unroll
    for (int nb = 0; nb < 8; nb++)
#pragma unroll
        for (int e = 0; e < 4; e++) cacc[nb][e] = 0.f;

#pragma unroll 1
    for (int jt = 0; jt < 4; jt++) {
        if (jt) __syncthreads();
#pragma unroll
        for (int n = 0; n < 4; n++) {
            const int e = tid + n * 256;
            const int t = e >> 4, cc = e & 15;
            const uint32_t off = (uint32_t)t * 272u
                + ((uint32_t)(cc ^ ((t >> 3) & 1)) << 4);
            const size_t g = (size_t)(r0g + t) * Dd + jt * 128 + cc * 8;
            cp16(khB + off, KhG + g);
            cp16(klB + off, KlG + g);
            cp16(qhB + off, QhG + g);
            cp16(qlB + off, QlG + g);
        }
        asm volatile("cp.async.commit_group;");
        asm volatile("cp.async.wait_group 0;");
        __syncthreads();
#pragma unroll
        for (int p = 0; p < 3; p++) {
            const uint32_t aT = mat ? (p < 2 ? qhB : qlB) : (p < 2 ? khB : klB);
            const uint32_t bT = (p == 1) ? klB : khB;
#pragma unroll
            for (int k = 0; k < 8; k++) {
                uint32_t a[4];
                {
                    const int r = mb * 16 + (lane & 15);
                    const int cc = k * 2 + (lane >> 4);
                    ldsm_x4(a, aT + r * 272u + ((uint32_t)(cc ^ ((r >> 3) & 1)) << 4));
                }
#pragma unroll
                for (int nb4 = 0; nb4 < 4; nb4++) {
                    uint32_t bb[4];
                    const int r = nb4 * 16 + (lane & 7) + ((lane >> 4) << 3);
                    const int cc = k * 2 + ((lane >> 3) & 1);
                    ldsm_x4(bb, bT + r * 272u + ((uint32_t)(cc ^ ((r >> 3) & 1)) << 4));
                    mma_bf16(cacc[nb4 * 2 + 0], a, bb[0], bb[1]);
                    mma_bf16(cacc[nb4 * 2 + 1], a, bb[2], bb[3]);
                }
            }
        }
    }
    __syncthreads();

    const size_t gbase = ((size_t)(b * NCH) + c) * (CH * CH);
    const int t0r = mb * 16 + fr, t1r = t0r + 8;
    if (mat == 0) {
        const float bt0 = Betad[r0g + t0r], bt1 = Betad[r0g + t1r];
#pragma unroll
        for (int nb = 0; nb < 8; nb++) {
            const int j = nb * 8 + fc;
            float2 o0, o1;
            o0.x = (j     < t0r) ? bt0 * cacc[nb][0] : 0.f;
            o0.y = (j + 1 < t0r) ? bt0 * cacc[nb][1] : 0.f;
            o1.x = (j     < t1r) ? bt1 * cacc[nb][2] : 0.f;
            o1.y = (j + 1 < t1r) ? bt1 * cacc[nb][3] : 0.f;
            *(float2*)&As[t0r * 66 + j] = o0;
            *(float2*)&As[t1r * 66 + j] = o1;
        }
    } else {
        unsigned short* Gh = (unsigned short*)GhG;
        unsigned short* Gl = (unsigned short*)GlG;
#pragma unroll
        for (int nb = 0; nb < 8; nb++) {
            const int j = nb * 8 + fc;
            float v00 = (j     <= t0r) ? cacc[nb][0] : 0.f;
            float v01 = (j + 1 <= t0r) ? cacc[nb][1] : 0.f;
            float v10 = (j     <= t1r) ? cacc[nb][2] : 0.f;
            float v11 = (j + 1 <= t1r) ? cacc[nb][3] : 0.f;
            *(uint32_t*)&Gh[gbase + t0r * 64 + j] = pack2(v00, v01, true);
            *(uint32_t*)&Gl[gbase + t0r * 64 + j] = pack2(v00, v01, false);
            *(uint32_t*)&Gh[gbase + t1r * 64 + j] = pack2(v10, v11, true);
            *(uint32_t*)&Gl[gbase + t1r * 64 + j] = pack2(v10, v11, false);
        }
    }
    for (int e = tid; e < 64 * 66; e += 256) Tm[e] = 0.f;
    __syncthreads();

    if (wid < 4) {
        const int r = lane & 15;
        float Lr[16], val[16];
#pragma unroll
        for (int j = 0; j < 16; j++) Lr[j] = As[(wid * 16 + r) * 66 + wid * 16 + j];
#pragma unroll
        for (int cc = 0; cc < 16; cc++) val[cc] = (r == cc) ? 1.f : 0.f;
#pragma unroll
        for (int j = 0; j < 15; j++) {
#pragma unroll
            for (int cc = 0; cc < 16; cc++) {
                if (cc <= j) {
                    float tjc = __shfl_sync(0xffffffffu, val[cc], j);
                    if (r > j) val[cc] -= Lr[j] * tjc;
                }
            }
        }
        if (lane < 16) {
#pragma unroll
            for (int cc = 0; cc < 16; cc++)
                Tm[(wid * 16 + r) * 66 + wid * 16 + cc] = val[cc];
        }
    }
    __syncthreads();

    {
        const int oi[6] = {1, 2, 3, 2, 3, 3};
        const int oj[6] = {0, 0, 0, 1, 1, 2};
        const int r = tid >> 4, cc = tid & 15;
#pragma unroll 1
        for (int s6 = 0; s6 < 6; s6++) {
            const int bi = oi[s6], bj = oj[s6];
            float w = 0.f;
            for (int k = bj; k < bi; k++)
#pragma unroll
                for (int m = 0; m < 16; m++)
                    w += As[(bi * 16 + r) * 66 + k * 16 + m] *
                         Tm[(k * 16 + m) * 66 + bj * 16 + cc];
            Ws[r * 17 + cc] = w;
            __syncthreads();
            float t2 = 0.f;
#pragma unroll
            for (int m = 0; m < 16; m++)
                t2 += Tm[(bi * 16 + r) * 66 + bi * 16 + m] * Ws[m * 17 + cc];
            Tm[(bi * 16 + r) * 66 + bj * 16 + cc] = -t2;
            __syncthreads();
        }
    }

    {
        unsigned short* Th = (unsigned short*)ThG;
        unsigned short* Tl = (unsigned short*)TlG;
        for (int e = tid; e < 2048; e += 256) {
            const int t = e >> 5, j = (e & 31) * 2;
            *(uint32_t*)&Th[gbase + t * 64 + j] =
                pack2(Tm[t * 66 + j], Tm[t * 66 + j + 1], true);
            *(uint32_t*)&Tl[gbase + t * 64 + j] =
                pack2(Tm[t * 66 + j], Tm[t * 66 + j + 1], false);
        }
    }
}

// ---------------- chunked delta-rule scan: all-mma, S in registers ----------
__global__ __launch_bounds__(256) void scan_kernel(
    const __nv_bfloat16* __restrict__ KhG, const __nv_bfloat16* __restrict__ KlG,
    const __nv_bfloat16* __restrict__ QhG, const __nv_bfloat16* __restrict__ QlG,
    const __nv_bfloat16* __restrict__ ThG, const __nv_bfloat16* __restrict__ TlG,
    const __nv_bfloat16* __restrict__ GhG, const __nv_bfloat16* __restrict__ GlG,
    const float* __restrict__ Vd, const float* __restrict__ Betad,
    __nv_bfloat16* __restrict__ OhG, __nv_bfloat16* __restrict__ OlG)
{
    extern __shared__ char sraw[];
    float* QSm   = (float*)(sraw + OFF_QS);
    float* Vb    = (float*)(sraw + OFF_VB);
    float* betas = (float*)(sraw + OFF_BETA);
    char* pKh = sraw + OFF_KH;  char* pKl = sraw + OFF_KL;
    char* pQh = sraw + OFF_QH;  char* pQl = sraw + OFF_QL;
    char* pSh = sraw + OFF_SH;  char* pSl = sraw + OFF_SL;
    char* pUh = sraw + OFF_UH;  char* pUl = sraw + OFF_UL;
    char* pTh = sraw + OFF_TH;  char* pTl = sraw + OFF_TL;
    char* pGh = sraw + OFF_GH;  char* pGl = sraw + OFF_GL;
    const uint32_t khB = smem_u32(pKh), klB = smem_u32(pKl);
    const uint32_t qhB = smem_u32(pQh), qlB = smem_u32(pQl);
    const uint32_t shB = smem_u32(pSh), slB = smem_u32(pSl);
    const uint32_t uhB = smem_u32(pUh), ulB = smem_u32(pUl);
    const uint32_t thB = smem_u32(pTh), tlB = smem_u32(pTl);
    const uint32_t ghB = smem_u32(pGh), glB = smem_u32(pGl);

    const int b = blockIdx.y;
    const int i0 = blockIdx.x * DV;
    const int tid = threadIdx.x;
    const int lane = tid & 31, wid = tid >> 5;
    const int fr = lane >> 2, fc = 2 * (lane & 3);

    auto stu = [&](float v, int i, int t) {
        unsigned short h, l; split2(v, h, l);
        const uint32_t off = (uint32_t)i * 144u
            + ((uint32_t)((t >> 3) ^ ((i >> 3) & 1)) << 4) + (t & 7) * 2;
        *(unsigned short*)(pUh + off) = h;
        *(unsigned short*)(pUl + off) = l;
    };

    // S state in registers: Sreg[jt][mi][n8][e] — thread (wid,lane) owns
    // S[rows mi*16+fr, mi*16+fr+8][cols jt*128 + wid*16 + n8*8 + fc, +1]
    float Sreg[4][2][2][4];
#pragma unroll
    for (int jt = 0; jt < 4; jt++)
#pragma unroll
        for (int mi = 0; mi < 2; mi++)
#pragma unroll
            for (int n8 = 0; n8 < 2; n8++)
#pragma unroll
                for (int e = 0; e < 4; e++) Sreg[jt][mi][n8][e] = 0.f;

    for (int c = 0; c < NCH; c++) {
        const int r0g = b * Tt + c * CH;
        const size_t gbase = ((size_t)(b * NCH) + c) * (CH * CH);

        // issue T/G staging (group) and phase-A jt=0 K/Q staging (group)
#pragma unroll
        for (int n = 0; n < 2; n++) {
            const int e = tid + n * 256;
            const int r = e >> 3, cc = e & 7;
            const uint32_t off = (uint32_t)r * 144u
                + ((uint32_t)(cc ^ ((r >> 3) & 1)) << 4);
            const size_t g = gbase + r * 64 + cc * 8;
            cp16(thB + off, ThG + g);
            cp16(tlB + off, TlG + g);
            cp16(ghB + off, GhG + g);
            cp16(glB + off, GlG + g);
        }
        asm volatile("cp.async.commit_group;");
#pragma unroll
        for (int n = 0; n < 4; n++) {
            const int e = tid + n * 256;
            const int t = e >> 4, cc = e & 15;
            const uint32_t off = (uint32_t)t * 272u
                + ((uint32_t)(cc ^ ((t >> 3) & 1)) << 4);
            const size_t g = (size_t)(r0g + t) * Dd + cc * 8;   // jt = 0
            cp16(khB + off, KhG + g);
            cp16(klB + off, KlG + g);
            cp16(qhB + off, QhG + g);
            cp16(qlB + off, QlG + g);
        }
        asm volatile("cp.async.commit_group;");
        for (int e = tid; e < CH * DV; e += 256) {
            const int t = e >> 5, i = e & 31;
            Vb[t * 34 + i] = Vd[(size_t)(r0g + t) * Dd + i0 + i];
        }
        if (tid < 64) betas[tid] = Betad[r0g + tid];

        // ---- Phase A ----
        const int mat = wid >> 2;
        const int mb  = wid & 3;
        float cacc[4][4];
#pragma unroll
        for (int nb = 0; nb < 4; nb++)
#pragma unroll
            for (int e = 0; e < 4; e++) cacc[nb][e] = 0.f;

#pragma unroll 1
        for (int jt = 0; jt < 4; jt++) {
            if (jt > 0) {
#pragma unroll
                for (int n = 0; n < 4; n++) {
                    const int e = tid + n * 256;
                    const int t = e >> 4, cc = e & 15;
                    const uint32_t off = (uint32_t)t * 272u
                        + ((uint32_t)(cc ^ ((t >> 3) & 1)) << 4);
                    const size_t g = (size_t)(r0g + t) * Dd + jt * 128 + cc * 8;
                    cp16(khB + off, KhG + g);
                    cp16(klB + off, KlG + g);
                    cp16(qhB + off, QhG + g);
                    cp16(qlB + off, QlG + g);
                }
                asm volatile("cp.async.commit_group;");
            }
            // convert S regs for tile jt -> SH/SL (register-direct, conflict-free)
#pragma unroll
            for (int mi = 0; mi < 2; mi++)
#pragma unroll
                for (int n8 = 0; n8 < 2; n8++) {
                    const int i0r = mi * 16 + fr, i1r = i0r + 8;
                    const int cc = wid * 16 + n8 * 8 + fc;
                    const uint32_t o0 = (uint32_t)i0r * 272u
                        + ((uint32_t)((cc >> 3) ^ ((i0r >> 3) & 1)) << 4) + (cc & 7) * 2;
                    const uint32_t o1 = (uint32_t)i1r * 272u
                        + ((uint32_t)((cc >> 3) ^ ((i1r >> 3) & 1)) << 4) + (cc & 7) * 2;
                    *(uint32_t*)(pSh + o0) = pack2(Sreg[jt][mi][n8][0], Sreg[jt][mi][n8][1], true);
                    *(uint32_t*)(pSl + o0) = pack2(Sreg[jt][mi][n8][0], Sreg[jt][mi][n8][1], false);
                    *(uint32_t*)(pSh + o1) = pack2(Sreg[jt][mi][n8][2], Sreg[jt][mi][n8][3], true);
                    *(uint32_t*)(pSl + o1) = pack2(Sreg[jt][mi][n8][2], Sreg[jt][mi][n8][3], false);
                }
            asm volatile("cp.async.wait_group 0;");
            __syncthreads();
            const uint32_t aHi = mat ? qhB : khB;
            const uint32_t aLo = mat ? qlB : klB;
#pragma unroll
            for (int k = 0; k < 8; k++) {
                uint32_t aH[4], aL[4], bH0[4], bH1[4], bX0[4], bX1[4];
                const int ra = mb * 16 + (lane & 15);
                const int ca = k * 2 + (lane >> 4);
                const uint32_t aoff = ra * 272u + ((uint32_t)(ca ^ ((ra >> 3) & 1)) << 4);
                const int rb = (lane & 7) + ((lane >> 4) << 3);
                const int cb = k * 2 + ((lane >> 3) & 1);
                const uint32_t boff0 = rb * 272u + ((uint32_t)(cb ^ ((rb >> 3) & 1)) << 4);
                const int rb2 = rb + 16;
                const uint32_t boff1 = rb2 * 272u + ((uint32_t)(cb ^ ((rb2 >> 3) & 1)) << 4);
                ldsm_x4(aH, aHi + aoff);
                ldsm_x4(bH0, shB + boff0);
                ldsm_x4(bH1, shB + boff1);
                mma_bf16(cacc[0], aH, bH0[0], bH0[1]);
                mma_bf16(cacc[1], aH, bH0[2], bH0[3]);
                mma_bf16(cacc[2], aH, bH1[0], bH1[1]);
                mma_bf16(cacc[3], aH, bH1[2], bH1[3]);
                ldsm_x4(bX0, slB + boff0);
                ldsm_x4(bX1, slB + boff1);
                mma_bf16(cacc[0], aH, bX0[0], bX0[1]);
                mma_bf16(cacc[1], aH, bX0[2], bX0[3]);
                mma_bf16(cacc[2], aH, bX1[0], bX1[1]);
                mma_bf16(cacc[3], aH, bX1[2], bX1[3]);
                ldsm_x4(aL, aLo + aoff);
                mma_bf16(cacc[0], aL, bH0[0], bH0[1]);
                mma_bf16(cacc[1], aL, bH0[2], bH0[3]);
                mma_bf16(cacc[2], aL, bH1[0], bH1[1]);
                mma_bf16(cacc[3], aL, bH1[2], bH1[3]);
            }
            __syncthreads();
        }

        // epilogue: warps 0-3 write rhs splits directly to UH/UL; 4-7 -> QSm
        {
            const int t0r = mb * 16 + fr, t1r = t0r + 8;
            if (mat == 0) {
                const float b0v = betas[t0r], b1v = betas[t1r];
#pragma unroll
                for (int nb = 0; nb < 4; nb++) {
                    const int i = nb * 8 + fc;
                    float2 v0 = *(float2*)&Vb[t0r * 34 + i];
                    float2 v1 = *(float2*)&Vb[t1r * 34 + i];
                    stu(b0v * (v0.x - cacc[nb][0]), i,     t0r);
                    stu(b0v * (v0.y - cacc[nb][1]), i + 1, t0r);
                    stu(b1v * (v1.x - cacc[nb][2]), i,     t1r);
                    stu(b1v * (v1.y - cacc[nb][3]), i + 1, t1r);
                }
            } else {
#pragma unroll
                for (int nb = 0; nb < 4; nb++) {
                    const int i = nb * 8 + fc;
                    *(float2*)&QSm[t0r * 34 + i] = make_float2(cacc[nb][0], cacc[nb][1]);
                    *(float2*)&QSm[t1r * 34 + i] = make_float2(cacc[nb][2], cacc[nb][3]);
                }
            }
        }
        __syncthreads();

        // Phase B': U = T @ rhs (frag reuse); epilogue writes U splits in place
        {
            const int mb2 = wid >> 1, nh = wid & 1;
            float du[2][4];
#pragma unroll
            for (int n8 = 0; n8 < 2; n8++)
#pragma unroll
                for (int e = 0; e < 4; e++) du[n8][e] = 0.f;
#pragma unroll
            for (int k = 0; k < 4; k++) {
                uint32_t aH[4], aL[4], bH[4], bX[4];
                const int ra = mb2 * 16 + (lane & 15);
                const int ca = k * 2 + (lane >> 4);
                const uint32_t aoff = ra * 144u + ((uint32_t)(ca ^ ((ra >> 3) & 1)) << 4);
                const int rb = nh * 16 + (lane & 7) + ((lane >> 4) << 3);
                const int cb = k * 2 + ((lane >> 3) & 1);
                const uint32_t boff = rb * 144u + ((uint32_t)(cb ^ ((rb >> 3) & 1)) << 4);
                ldsm_x4(aH, thB + aoff);
                ldsm_x4(bH, uhB + boff);
                mma_bf16(du[0], aH, bH[0], bH[1]);
                mma_bf16(du[1], aH, bH[2], bH[3]);
                ldsm_x4(bX, ulB + boff);
                mma_bf16(du[0], aH, bX[0], bX[1]);
                mma_bf16(du[1], aH, bX[2], bX[3]);
                ldsm_x4(aL, tlB + aoff);
                mma_bf16(du[0], aL, bH[0], bH[1]);
                mma_bf16(du[1], aL, bH[2], bH[3]);
            }
            __syncthreads();   // rhs reads complete before overwrite
            const int t0r = mb2 * 16 + fr, t1r = t0r + 8;
#pragma unroll
            for (int n8 = 0; n8 < 2; n8++) {
                const int i = nh * 16 + n8 * 8 + fc;
                stu(du[n8][0], i,     t0r);
                stu(du[n8][1], i + 1, t0r);
                stu(du[n8][2], i,     t1r);
                stu(du[n8][3], i + 1, t1r);
            }
        }
        __syncthreads();

        // issue phase-D jt=0 K staging into K slot (overlaps phase C')
#pragma unroll
        for (int n = 0; n < 4; n++) {
            const int e = tid + n * 256;
            const int t = e >> 4, cc = e & 15;
            const uint32_t off = (uint32_t)t * 272u
                + ((uint32_t)(cc ^ ((t >> 3) & 1)) << 4);
            const size_t g = (size_t)(r0g + t) * Dd + cc * 8;    // jt = 0
            cp16(khB + off, KhG + g);
            cp16(klB + off, KlG + g);
        }
        asm volatile("cp.async.commit_group;");

        // Phase C': O = QS + G @ U (frag reuse, split bf16 output)
        {
            const int mb2 = wid >> 1, nh = wid & 1;
            const int t0r = mb2 * 16 + fr, t1r = t0r + 8;
            float du[2][4];
#pragma unroll
            for (int n8 = 0; n8 < 2; n8++) {
                const int i = nh * 16 + n8 * 8 + fc;
                float2 q0 = *(float2*)&QSm[t0r * 34 + i];
                float2 q1 = *(float2*)&QSm[t1r * 34 + i];
                du[n8][0] = q0.x; du[n8][1] = q0.y;
                du[n8][2] = q1.x; du[n8][3] = q1.y;
            }
#pragma unroll
            for (int k = 0; k < 4; k++) {
                uint32_t aH[4], aL[4], bH[4], bX[4];
                const int ra = mb2 * 16 + (lane & 15);
                const int ca = k * 2 + (lane >> 4);
                const uint32_t aoff = ra * 144u + ((uint32_t)(ca ^ ((ra >> 3) & 1)) << 4);
                const int rb = nh * 16 + (lane & 7) + ((lane >> 4) << 3);
                const int cb = k * 2 + ((lane >> 3) & 1);
                const uint32_t boff = rb * 144u + ((uint32_t)(cb ^ ((rb >> 3) & 1)) << 4);
                ldsm_x4(aH, ghB + aoff);
                ldsm_x4(bH, uhB + boff);
                mma_bf16(du[0], aH, bH[0], bH[1]);
                mma_bf16(du[1], aH, bH[2], bH[3]);
                ldsm_x4(bX, ulB + boff);
                mma_bf16(du[0], aH, bX[0], bX[1]);
                mma_bf16(du[1], aH, bX[2], bX[3]);
                ldsm_x4(aL, glB + aoff);
                mma_bf16(du[0], aL, bH[0], bH[1]);
                mma_bf16(du[1], aL, bH[2], bH[3]);
            }
            unsigned short* oh = (unsigned short*)OhG;
            unsigned short* ol = (unsigned short*)OlG;
#pragma unroll
            for (int n8 = 0; n8 < 2; n8++) {
                const int i = nh * 16 + n8 * 8 + fc;
                const size_t g0 = (size_t)(r0g + t0r) * Dd + i0 + i;
                const size_t g1 = (size_t)(r0g + t1r) * Dd + i0 + i;
                *(uint32_t*)&oh[g0] = pack2(du[n8][0], du[n8][1], true);
                *(uint32_t*)&ol[g0] = pack2(du[n8][0], du[n8][1], false);
                *(uint32_t*)&oh[g1] = pack2(du[n8][2], du[n8][3], true);
                *(uint32_t*)&ol[g1] = pack2(du[n8][2], du[n8][3], false);
            }
        }

        // Phase D: S += U^T @ K  (S in registers; double-buffered staging)
#pragma unroll 1
        for (int jt = 0; jt < 4; jt++) {
            const uint32_t curH = (jt & 1) ? qhB : khB;
            const uint32_t curL = (jt & 1) ? qlB : klB;
            if (jt + 1 < 4) {
                const uint32_t nxtH = ((jt + 1) & 1) ? qhB : khB;
                const uint32_t nxtL = ((jt + 1) & 1) ? qlB : klB;
#pragma unroll
                for (int n = 0; n < 4; n++) {
                    const int e = tid + n * 256;
                    const int t = e >> 4, cc = e & 15;
                    const uint32_t off = (uint32_t)t * 272u
                        + ((uint32_t)(cc ^ ((t >> 3) & 1)) << 4);
                    const size_t g = (size_t)(r0g + t) * Dd + (jt + 1) * 128 + cc * 8;
                    cp16(nxtH + off, KhG + g);
                    cp16(nxtL + off, KlG + g);
                }
                asm volatile("cp.async.commit_group;");
                asm volatile("cp.async.wait_group 1;");
            } else {
                asm volatile("cp.async.wait_group 0;");
            }
            __syncthreads();

#pragma unroll
            for (int k = 0; k < 4; k++) {
                uint32_t aH0[4], aH1[4], aL0[4], aL1[4], bH[4], bX[4];
                const int r = lane & 15;
                const int ca = k * 2 + (lane >> 4);
                const uint32_t aoff0 = r * 144u + ((uint32_t)(ca ^ ((r >> 3) & 1)) << 4);
                const int r2 = 16 + (lane & 15);
                const uint32_t aoff1 = r2 * 144u + ((uint32_t)(ca ^ ((r2 >> 3) & 1)) << 4);
                const int tr = k * 16 + (lane & 15);
                const int cb = wid * 2 + (lane >> 4);
                const uint32_t boff = tr * 272u + ((uint32_t)(cb ^ ((tr >> 3) & 1)) << 4);
                ldsm_x4(aH0, uhB + aoff0);
                ldsm_x4(aH1, uhB + aoff1);
                ldsm_x4t(bH, curH + boff);
                mma_bf16(Sreg[jt][0][0], aH0, bH[0], bH[1]);
                mma_bf16(Sreg[jt][0][1], aH0, bH[2], bH[3]);
                mma_bf16(Sreg[jt][1][0], aH1, bH[0], bH[1]);
                mma_bf16(Sreg[jt][1][1], aH1, bH[2], bH[3]);
                ldsm_x4t(bX, curL + boff);
                mma_bf16(Sreg[jt][0][0], aH0, bX[0], bX[1]);
                mma_bf16(Sreg[jt][0][1], aH0, bX[2], bX[3]);
                mma_bf16(Sreg[jt][1][0], aH1, bX[0], bX[1]);
                mma_bf16(Sreg[jt][1][1], aH1, bX[2], bX[3]);
                ldsm_x4(aL0, ulB + aoff0);
                ldsm_x4(aL1, ulB + aoff1);
                mma_bf16(Sreg[jt][0][0], aL0, bH[0], bH[1]);
                mma_bf16(Sreg[jt][0][1], aL0, bH[2], bH[3]);
                mma_bf16(Sreg[jt][1][0], aL1, bH[0], bH[1]);
                mma_bf16(Sreg[jt][1][1], aL1, bH[2], bH[3]);
            }
            __syncthreads();
        }
    }
}

extern "C" void kernel_launch(void* const* d_in, const int* in_sizes, int n_in,
                              void* d_out, int out_size)
{
    const float* x     = (const float*)d_in[0];
    const float* Wq    = (const float*)d_in[1];
    const float* bq    = (const float*)d_in[2];
    const float* Wk    = (const float*)d_in[3];
    const float* bk    = (const float*)d_in[4];
    const float* Wv    = (const float*)d_in[5];
    const float* bv    = (const float*)d_in[6];
    const float* Wbeta = (const float*)d_in[7];
    const float* bbeta = (const float*)d_in[8];
    const float* Wo    = (const float*)d_in[9];
    const float* bo    = (const float*)d_in[10];
    float* out = (float*)d_out;

    float *pK, *pV, *pBeta;
    cudaGetSymbolAddress((void**)&pK, g_K);
    cudaGetSymbolAddress((void**)&pV, g_V);
    cudaGetSymbolAddress((void**)&pBeta, g_Beta);

    __nv_bfloat16 *pxh, *pxl, *poh, *pol, *pkh, *pkl, *pqh, *pql;
    __nv_bfloat16 *pTh, *pTl, *pGh, *pGl;
    __nv_bfloat16 *pwqh, *pwql, *pwkh, *pwkl, *pwvh, *pwvl, *pwoh, *pwol;
    cudaGetSymbolAddress((void**)&pxh, g_xh);
    cudaGetSymbolAddress((void**)&pxl, g_xl);
    cudaGetSymbolAddress((void**)&poh, g_oh);
    cudaGetSymbolAddress((void**)&pol, g_ol);
    cudaGetSymbolAddress((void**)&pkh, g_kh);
    cudaGetSymbolAddress((void**)&pkl, g_kl);
    cudaGetSymbolAddress((void**)&pqh, g_qh);
    cudaGetSymbolAddress((void**)&pql, g_ql);
    cudaGetSymbolAddress((void**)&pTh, g_Th);
    cudaGetSymbolAddress((void**)&pTl, g_Tl);
    cudaGetSymbolAddress((void**)&pGh, g_Gh);
    cudaGetSymbolAddress((void**)&pGl, g_Gl);
    cudaGetSymbolAddress((void**)&pwqh, g_wqh);
    cudaGetSymbolAddress((void**)&pwql, g_wql);
    cudaGetSymbolAddress((void**)&pwkh, g_wkh);
    cudaGetSymbolAddress((void**)&pwkl, g_wkl);
    cudaGetSymbolAddress((void**)&pwvh, g_wvh);
    cudaGetSymbolAddress((void**)&pwvl, g_wvl);
    cudaGetSymbolAddress((void**)&pwoh, g_woh);
    cudaGetSymbolAddress((void**)&pwol, g_wol);

    cudaFuncSetAttribute(scan_kernel,
                         cudaFuncAttributeMaxDynamicSharedMemorySize, SCAN_SMEM);
    cudaFuncSetAttribute(tgemm_mma_kernel,
                         cudaFuncAttributeMaxDynamicSharedMemorySize, TG_SMEM);
    cudaFuncSetAttribute(tgemm_qkv_kernel,
                         cudaFuncAttributeMaxDynamicSharedMemorySize, TG_SMEM);
    cudaFuncSetAttribute(chunk_ag_mma_kernel,
                         cudaFuncAttributeMaxDynamicSharedMemorySize, AG_SMEM);

    const int nx4 = BT * Dd / 4;
    const int nw4 = Dd * Dd / 4;
    split_kernel<<<(nx4 + 255) / 256, 256>>>(x, pxh, pxl, nx4);
    split_w_kernel<<<dim3((nw4 + 255) / 256, 4), 256>>>(
        Wq, Wk, Wv, Wo, pwqh, pwql, pwkh, pwkl, pwvh, pwvl, pwoh, pwol, nw4);

    tgemm_qkv_kernel<<<dim3(12, BT / 128), 256, TG_SMEM>>>(
        pxh, pxl, pwqh, pwql, pwkh, pwkl, pwvh, pwvl, bq, bk, bv,
        pqh, pql, pK, pV);

    norm_beta_kernel<<<BT, 128>>>(pK, Wbeta, bbeta, pBeta, pkh, pkl);

    chunk_ag_mma_kernel<<<dim3(NCH, Bb), 256, AG_SMEM>>>(
        pkh, pkl, pqh, pql, pBeta, pTh, pTl, pGh, pGl);

    scan_kernel<<<dim3(NVT, Bb), 256, SCAN_SMEM>>>(
        pkh, pkl, pqh, pql, pTh, pTl, pGh, pGl, pV, pBeta, poh, pol);

    tgemm_mma_kernel<<<dim3(4, BT / 128), 256, TG_SMEM>>>(
        poh, pol, pwoh, pwol, bo, out);
}